// round 2
// baseline (speedup 1.0000x reference)
#include <cuda_runtime.h>
#include <cuda_bf16.h>
#include <cstdint>

// Problem constants: B=16, H=16, M=256, N=576, D=1024
#define BB 16
#define HH 16
#define MM 256
#define NN 576
#define DD 1024

#define EPSF 1e-8f
#define MU_C (1.0f / 576.0f)
#define FI_C (1.0f / 1.1f)

// ---------------- device scratch ----------------
__device__ __nv_bfloat16 g_xb[BB * NN * DD];   // visual feats bf16 (raw)
__device__ __nv_bfloat16 g_yb[BB * MM * DD];   // text feats bf16 (raw)
__device__ float g_inv_nx[BB * NN];
__device__ float g_inv_ny[BB * MM];
__device__ float g_K[BB * MM * NN];            // exp(-cost/eps)
__device__ float g_Kv[BB * MM];
__device__ float g_Ktu[BB * NN];
__device__ float g_partial[BB * MM];

// ---------------- helpers ----------------
__device__ __forceinline__ float warp_sum(float v) {
#pragma unroll
    for (int o = 16; o; o >>= 1) v += __shfl_xor_sync(0xffffffffu, v, o);
    return v;
}

// 256-thread block sum; red must hold >= 8 floats
__device__ __forceinline__ float block_sum256(float v, volatile float* red) {
    int tid = threadIdx.x;
    float w = warp_sum(v);
    if ((tid & 31) == 0) red[tid >> 5] = w;
    __syncthreads();
    if (tid < 32) {
        float r = (tid < 8) ? red[tid] : 0.0f;
        r = warp_sum(r);
        if (tid == 0) red[0] = r;
    }
    __syncthreads();
    float out = red[0];
    __syncthreads();
    return out;
}

__device__ __forceinline__ void ldsm4(uint32_t* r, uint32_t addr) {
    asm volatile("ldmatrix.sync.aligned.m8n8.x4.shared.b16 {%0,%1,%2,%3}, [%4];"
                 : "=r"(r[0]), "=r"(r[1]), "=r"(r[2]), "=r"(r[3]) : "r"(addr));
}

__device__ __forceinline__ void mma16816(float* c, const uint32_t* a, const uint32_t* b) {
    asm volatile(
        "mma.sync.aligned.m16n8k16.row.col.f32.bf16.bf16.f32 "
        "{%0,%1,%2,%3}, {%4,%5,%6,%7}, {%8,%9}, {%0,%1,%2,%3};"
        : "+f"(c[0]), "+f"(c[1]), "+f"(c[2]), "+f"(c[3])
        : "r"(a[0]), "r"(a[1]), "r"(a[2]), "r"(a[3]), "r"(b[0]), "r"(b[1]));
}

// ---------------- kernel 1: norms + bf16 conversion ----------------
// one warp per feature row (B*N visual rows then B*M text rows)
__global__ void __launch_bounds__(256) prep_kernel(const float* __restrict__ visual,
                                                   const float* __restrict__ text) {
    int warp = blockIdx.x * 8 + (threadIdx.x >> 5);
    int lane = threadIdx.x & 31;
    const int VROWS = BB * NN;
    const float* src;
    __nv_bfloat16* dst;
    float* invp;
    if (warp < VROWS) {
        src = visual + (size_t)warp * DD;
        dst = g_xb + (size_t)warp * DD;
        invp = g_inv_nx + warp;
    } else {
        int r = warp - VROWS;
        src = text + (size_t)r * DD;
        dst = g_yb + (size_t)r * DD;
        invp = g_inv_ny + r;
    }
    const float4* s4 = (const float4*)src;
    uint2* d2 = (uint2*)dst;
    float ss = 0.0f;
#pragma unroll
    for (int i = 0; i < 8; ++i) {
        float4 v = s4[lane + 32 * i];
        ss += v.x * v.x + v.y * v.y + v.z * v.z + v.w * v.w;
        uint32_t lo = (uint32_t)__bfloat16_as_ushort(__float2bfloat16_rn(v.x))
                    | ((uint32_t)__bfloat16_as_ushort(__float2bfloat16_rn(v.y)) << 16);
        uint32_t hi = (uint32_t)__bfloat16_as_ushort(__float2bfloat16_rn(v.z))
                    | ((uint32_t)__bfloat16_as_ushort(__float2bfloat16_rn(v.w)) << 16);
        d2[lane + 32 * i] = make_uint2(lo, hi);
    }
    ss = warp_sum(ss);
    if (lane == 0) *invp = rsqrtf(ss + 1e-12f);
}

// ---------------- kernel 2: HMMA bf16 GEMM + exp epilogue ----------------
// grid: (nt=9, mt=2, b=16); block 256 = 8 warps (4 x 2).
// Block tile: M=128 x N=64; warp tile 32x32; K staged by 64.
// SMEM swizzle: 128B rows of 8 x 16B chunks; chunk' = chunk ^ (row & 7).
__global__ void __launch_bounds__(256) gemm_expK_kernel() {
    __shared__ __align__(16) char sa_g[128 * 128];  // A: 128 rows x 64 bf16
    __shared__ __align__(16) char sb_g[64 * 128];   // B:  64 rows x 64 bf16
    uint32_t SA = (uint32_t)__cvta_generic_to_shared(sa_g);
    uint32_t SB = (uint32_t)__cvta_generic_to_shared(sb_g);

    int tid = threadIdx.x, wid = tid >> 5, lane = tid & 31;
    int nt = blockIdx.x, mt = blockIdx.y, b = blockIdx.z;
    int wm = wid & 3, wn = wid >> 2;  // warp coords: 4 in M, 2 in N

    const __nv_bfloat16* Abase = g_yb + ((size_t)(b * MM + mt * 128)) * DD;  // text (M)
    const __nv_bfloat16* Bbase = g_xb + ((size_t)(b * NN + nt * 64)) * DD;   // visual (N)

    float acc[2][4][4];
#pragma unroll
    for (int i = 0; i < 2; ++i)
#pragma unroll
        for (int j = 0; j < 4; ++j)
#pragma unroll
            for (int k = 0; k < 4; ++k) acc[i][j][k] = 0.0f;

    // ldmatrix address precompute (constant across k iterations except chunk idx)
    int a_row0 = wm * 32 + ((lane >> 3) & 1) * 8 + (lane & 7);       // for m-subtile 0
    int a_chunk_sel = (lane >> 4);                                   // 0/1 within k16
    int b_row0 = wn * 32 + (lane >> 4) * 8 + (lane & 7);             // for n-subtile 0-1
    int b_chunk_sel = ((lane >> 3) & 1);

    for (int s = 0; s < 16; ++s) {
        int kb = s * 64;
        // ---- load A tile: 128 rows x 8 chunks (16B) ----
#pragma unroll
        for (int q = 0; q < 4; ++q) {
            int c = tid + 256 * q;
            int row = c >> 3, cc = c & 7;
            uint4 v = *(const uint4*)(Abase + (size_t)row * DD + kb + cc * 8);
            *(uint4*)(sa_g + row * 128 + (cc ^ (row & 7)) * 16) = v;
        }
        // ---- load B tile: 64 rows x 8 chunks ----
#pragma unroll
        for (int q = 0; q < 2; ++q) {
            int c = tid + 256 * q;
            int row = c >> 3, cc = c & 7;
            uint4 v = *(const uint4*)(Bbase + (size_t)row * DD + kb + cc * 8);
            *(uint4*)(sb_g + row * 128 + (cc ^ (row & 7)) * 16) = v;
        }
        __syncthreads();

#pragma unroll
        for (int kk = 0; kk < 4; ++kk) {
            uint32_t a0[4], a1[4], bA[4], bB[4];
            {   // A m-subtile 0 (rows wm*32 .. +15)
                int row = a_row0;
                int ch = kk * 2 + a_chunk_sel;
                ldsm4(a0, SA + row * 128 + ((ch ^ (row & 7)) * 16));
                // A m-subtile 1 (rows +16)
                row = a_row0 + 16;
                ldsm4(a1, SA + row * 128 + ((ch ^ (row & 7)) * 16));
            }
            {   // B n-subtiles 0-1 (n 0..15 of warp) and 2-3 (n 16..31)
                int row = b_row0;
                int ch = kk * 2 + b_chunk_sel;
                ldsm4(bA, SB + row * 128 + ((ch ^ (row & 7)) * 16));
                row = b_row0 + 16;
                ldsm4(bB, SB + row * 128 + ((ch ^ (row & 7)) * 16));
            }
            mma16816(acc[0][0], a0, bA + 0);
            mma16816(acc[0][1], a0, bA + 2);
            mma16816(acc[0][2], a0, bB + 0);
            mma16816(acc[0][3], a0, bB + 2);
            mma16816(acc[1][0], a1, bA + 0);
            mma16816(acc[1][1], a1, bA + 2);
            mma16816(acc[1][2], a1, bB + 0);
            mma16816(acc[1][3], a1, bB + 2);
        }
        __syncthreads();
    }

    // ---- epilogue: scale by inv-norms, exp((cos-1)*10), write g_K ----
    int mrow_base = mt * 128 + wm * 32 + (lane >> 2);
    int ncol_base = nt * 64 + wn * 32 + (lane & 3) * 2;
    const float* invx = g_inv_nx + b * NN;
    const float* invy = g_inv_ny + b * MM;
#pragma unroll
    for (int mi = 0; mi < 2; ++mi) {
#pragma unroll
        for (int half = 0; half < 2; ++half) {  // c0c1 (row) vs c2c3 (row+8)
            int m = mrow_base + mi * 16 + half * 8;
            float invm = invy[m];
            float* out = g_K + ((size_t)(b * MM + m)) * NN;
#pragma unroll
            for (int ni = 0; ni < 4; ++ni) {
                int n = ncol_base + ni * 8;
                float c0 = acc[mi][ni][half * 2 + 0];
                float c1 = acc[mi][ni][half * 2 + 1];
                float s0 = c0 * invm * invx[n];
                float s1 = c1 * invm * invx[n + 1];
                float2 e;
                e.x = __expf((s0 - 1.0f) * 10.0f);
                e.y = __expf((s1 - 1.0f) * 10.0f);
                *(float2*)(out + n) = e;
            }
        }
    }
}

// ---------------- Sinkhorn: Kv = K v  (v = f(Ktu) computed on the fly) ----------
// grid 512 blocks x 256 threads; block = 8 rows of one batch b
__global__ void __launch_bounds__(256) sink_u_kernel(int first) {
    __shared__ float vsm[NN];
    int blk = blockIdx.x, tid = threadIdx.x;
    int b = blk >> 5;  // 32 blocks per batch (256 rows / 8)
    for (int j = tid; j < NN; j += 256)
        vsm[j] = first ? 1.0f : __powf(MU_C / (g_Ktu[b * NN + j] + EPSF), FI_C);
    __syncthreads();
    int wid = tid >> 5, lane = tid & 31;
    int row = blk * 8 + wid;  // global (b,m) row
    const float* Kr = g_K + (size_t)row * NN;
    float acc = 0.0f;
#pragma unroll
    for (int it = 0; it < 18; ++it) {
        int j = lane + it * 32;
        acc += Kr[j] * vsm[j];
    }
    acc = warp_sum(acc);
    if (lane == 0) g_Kv[row] = acc;
}

// ---------------- Sinkhorn: Ktu = K^T u (u = f(Kv) computed on the fly) ---------
// grid (nc=9, b=16) x 256 threads; columns coalesced, m split 4-way
__global__ void __launch_bounds__(256) sink_v_kernel(const float* __restrict__ mask) {
    __shared__ float usm[MM];
    __shared__ float red[8];
    __shared__ float red2[256];
    int nc = blockIdx.x, b = blockIdx.y, tid = threadIdx.x;
    float mv = mask[b * MM + tid];
    float msum = block_sum256(mv, red);
    float nu = mv / (msum + EPSF);
    usm[tid] = __powf(nu / (g_Kv[b * MM + tid] + EPSF), FI_C);
    __syncthreads();
    int nl = tid & 63, mq = tid >> 6;
    const float* Kb = g_K + (size_t)b * MM * NN + nc * 64 + nl;
    float acc = 0.0f;
#pragma unroll 8
    for (int m = mq; m < MM; m += 4)
        acc += Kb[(size_t)m * NN] * usm[m];
    red2[tid] = acc;
    __syncthreads();
    if (mq == 0)
        g_Ktu[b * NN + nc * 64 + nl] =
            red2[nl] + red2[nl + 64] + red2[nl + 128] + red2[nl + 192];
}

// ---------------- loss: per (b,m) teacher row dotted with sum_h log(student) ----
__global__ void __launch_bounds__(256) loss_kernel(const float* __restrict__ student,
                                                   const float* __restrict__ mask) {
    __shared__ float psm[NN];
    __shared__ float red[8];
    int blk = blockIdx.x, tid = threadIdx.x;
    int b = blk >> 8, m = blk & 255;
    float mv = mask[b * MM + tid];
    float msum = block_sum256(mv, red);
    float mk = mask[b * MM + m];
    float u = __powf((mk / (msum + EPSF)) / (g_Kv[blk] + EPSF), FI_C);
    const float* Kr = g_K + (size_t)blk * NN;
    float rs = 0.0f;
    for (int j = tid; j < NN; j += 256) {
        float v = __powf(MU_C / (g_Ktu[b * NN + j] + EPSF), FI_C);
        float p = u * Kr[j] * v;
        psm[j] = p;
        rs += p;
    }
    float rowsum = block_sum256(rs, red);  // also makes psm visible
    float acc = 0.0f;
    const float* sbase = student + ((size_t)(b * HH) * MM + m) * NN;
#pragma unroll
    for (int h = 0; h < HH; ++h) {
        const float* sh = sbase + (size_t)h * MM * NN;
        for (int j = tid; j < NN; j += 256)
            acc += psm[j] * __logf(sh[j] + EPSF);
    }
    float tot = block_sum256(acc, red);
    if (tid == 0) g_partial[blk] = -(tot / (rowsum + EPSF)) * mk;
}

// ---------------- final reduce ----------------
__global__ void __launch_bounds__(256) reduce_kernel(float* __restrict__ out) {
    __shared__ float red[8];
    int tid = threadIdx.x;
    float s = 0.0f;
    for (int i = tid; i < BB * MM; i += 256) s += g_partial[i];
    float t = block_sum256(s, red);
    if (tid == 0) out[0] = t * (1.0f / (float)(BB * HH * MM));
}

// ---------------- launch ----------------
extern "C" void kernel_launch(void* const* d_in, const int* in_sizes, int n_in,
                              void* d_out, int out_size) {
    const float *student = nullptr, *visual = nullptr, *text = nullptr, *mask = nullptr;
    for (int i = 0; i < n_in; ++i) {
        long sz = in_sizes[i];
        if (sz == (long)BB * HH * MM * NN) student = (const float*)d_in[i];
        else if (sz == (long)BB * NN * DD) visual = (const float*)d_in[i];
        else if (sz == (long)BB * MM * DD) text = (const float*)d_in[i];
        else if (sz == (long)BB * MM) mask = (const float*)d_in[i];
    }
    float* out = (float*)d_out;

    prep_kernel<<<(BB * NN + BB * MM) / 8, 256>>>(visual, text);
    gemm_expK_kernel<<<dim3(NN / 64, MM / 128, BB), 256>>>();
    for (int it = 0; it < 5; ++it) {
        sink_u_kernel<<<BB * MM / 8, 256>>>(it == 0 ? 1 : 0);
        sink_v_kernel<<<dim3(NN / 64, BB), 256>>>(mask);
    }
    loss_kernel<<<BB * MM, 256>>>(student, mask);
    reduce_kernel<<<1, 256>>>(out);
}

// round 3
// speedup vs baseline: 1.4965x; 1.4965x over previous
#include <cuda_runtime.h>
#include <cuda_bf16.h>
#include <cstdint>

// Problem constants: B=16, H=16, M=256, N=576, D=1024
#define BB 16
#define HH 16
#define MM 256
#define NN 576
#define DD 1024

#define EPSF 1e-8f
#define MU_C (1.0f / 576.0f)
#define FI_C (1.0f / 1.1f)

// ---------------- device scratch ----------------
__device__ __nv_bfloat16 g_xb[BB * NN * DD];   // visual feats bf16 (raw)
__device__ __nv_bfloat16 g_yb[BB * MM * DD];   // text feats bf16 (raw)
__device__ float g_inv_nx[BB * NN];
__device__ float g_inv_ny[BB * MM];
__device__ float g_K[BB * MM * NN];            // exp(-cost/eps)
__device__ float g_u[BB * MM];                 // Sinkhorn u
__device__ float g_v[BB * NN];                 // Sinkhorn v
__device__ float g_nu[BB * MM];
__device__ float g_partial[BB * MM];
__device__ unsigned g_bar_cnt;
__device__ volatile unsigned g_bar_gen;

// ---------------- helpers ----------------
__device__ __forceinline__ float warp_sum(float v) {
#pragma unroll
    for (int o = 16; o; o >>= 1) v += __shfl_xor_sync(0xffffffffu, v, o);
    return v;
}

__device__ __forceinline__ float block_sum256(float v, volatile float* red) {
    int tid = threadIdx.x;
    float w = warp_sum(v);
    if ((tid & 31) == 0) red[tid >> 5] = w;
    __syncthreads();
    if (tid < 32) {
        float r = (tid < 8) ? red[tid] : 0.0f;
        r = warp_sum(r);
        if (tid == 0) red[0] = r;
    }
    __syncthreads();
    float out = red[0];
    __syncthreads();
    return out;
}

__device__ __forceinline__ float block_sum512(float v, volatile float* red) {
    int tid = threadIdx.x;
    float w = warp_sum(v);
    if ((tid & 31) == 0) red[tid >> 5] = w;
    __syncthreads();
    if (tid < 32) {
        float r = (tid < 16) ? red[tid] : 0.0f;
        r = warp_sum(r);
        if (tid == 0) red[0] = r;
    }
    __syncthreads();
    float out = red[0];
    __syncthreads();
    return out;
}

// grid-wide barrier: grid must be a single resident wave (grid <= 148)
__device__ __forceinline__ void grid_bar(int nblk) {
    __threadfence();
    __syncthreads();
    if (threadIdx.x == 0) {
        unsigned gen = g_bar_gen;
        if (atomicAdd(&g_bar_cnt, 1u) == (unsigned)(nblk - 1)) {
            g_bar_cnt = 0;
            __threadfence();
            g_bar_gen = gen + 1;
        } else {
            while (g_bar_gen == gen) {}
        }
        __threadfence();
    }
    __syncthreads();
}

__device__ __forceinline__ void ldsm4(uint32_t* r, uint32_t addr) {
    asm volatile("ldmatrix.sync.aligned.m8n8.x4.shared.b16 {%0,%1,%2,%3}, [%4];"
                 : "=r"(r[0]), "=r"(r[1]), "=r"(r[2]), "=r"(r[3]) : "r"(addr));
}

__device__ __forceinline__ void mma16816(float* c, const uint32_t* a, const uint32_t* b) {
    asm volatile(
        "mma.sync.aligned.m16n8k16.row.col.f32.bf16.bf16.f32 "
        "{%0,%1,%2,%3}, {%4,%5,%6,%7}, {%8,%9}, {%0,%1,%2,%3};"
        : "+f"(c[0]), "+f"(c[1]), "+f"(c[2]), "+f"(c[3])
        : "r"(a[0]), "r"(a[1]), "r"(a[2]), "r"(a[3]), "r"(b[0]), "r"(b[1]));
}

// ---------------- kernel 1: norms + bf16 conversion ----------------
__global__ void __launch_bounds__(256) prep_kernel(const float* __restrict__ visual,
                                                   const float* __restrict__ text) {
    int warp = blockIdx.x * 8 + (threadIdx.x >> 5);
    int lane = threadIdx.x & 31;
    const int VROWS = BB * NN;
    const float* src;
    __nv_bfloat16* dst;
    float* invp;
    if (warp < VROWS) {
        src = visual + (size_t)warp * DD;
        dst = g_xb + (size_t)warp * DD;
        invp = g_inv_nx + warp;
    } else {
        int r = warp - VROWS;
        src = text + (size_t)r * DD;
        dst = g_yb + (size_t)r * DD;
        invp = g_inv_ny + r;
    }
    const float4* s4 = (const float4*)src;
    uint2* d2 = (uint2*)dst;
    float ss = 0.0f;
#pragma unroll
    for (int i = 0; i < 8; ++i) {
        float4 v = __ldcs(&s4[lane + 32 * i]);
        ss += v.x * v.x + v.y * v.y + v.z * v.z + v.w * v.w;
        uint32_t lo = (uint32_t)__bfloat16_as_ushort(__float2bfloat16_rn(v.x))
                    | ((uint32_t)__bfloat16_as_ushort(__float2bfloat16_rn(v.y)) << 16);
        uint32_t hi = (uint32_t)__bfloat16_as_ushort(__float2bfloat16_rn(v.z))
                    | ((uint32_t)__bfloat16_as_ushort(__float2bfloat16_rn(v.w)) << 16);
        d2[lane + 32 * i] = make_uint2(lo, hi);
    }
    ss = warp_sum(ss);
    if (lane == 0) *invp = rsqrtf(ss + 1e-12f);
}

// ---------------- kernel 2: HMMA bf16 GEMM + exp epilogue ----------------
// grid: (nt=9, mt=2, b=16); block 256 = 8 warps (4 x 2).
__global__ void __launch_bounds__(256) gemm_expK_kernel() {
    __shared__ __align__(16) char sa_g[128 * 128];
    __shared__ __align__(16) char sb_g[64 * 128];
    uint32_t SA = (uint32_t)__cvta_generic_to_shared(sa_g);
    uint32_t SB = (uint32_t)__cvta_generic_to_shared(sb_g);

    int tid = threadIdx.x, wid = tid >> 5, lane = tid & 31;
    int nt = blockIdx.x, mt = blockIdx.y, b = blockIdx.z;
    int wm = wid & 3, wn = wid >> 2;

    const __nv_bfloat16* Abase = g_yb + ((size_t)(b * MM + mt * 128)) * DD;
    const __nv_bfloat16* Bbase = g_xb + ((size_t)(b * NN + nt * 64)) * DD;

    float acc[2][4][4];
#pragma unroll
    for (int i = 0; i < 2; ++i)
#pragma unroll
        for (int j = 0; j < 4; ++j)
#pragma unroll
            for (int k = 0; k < 4; ++k) acc[i][j][k] = 0.0f;

    int a_row0 = wm * 32 + ((lane >> 3) & 1) * 8 + (lane & 7);
    int a_chunk_sel = (lane >> 4);
    int b_row0 = wn * 32 + (lane >> 4) * 8 + (lane & 7);
    int b_chunk_sel = ((lane >> 3) & 1);

    // per-thread staging coords
    int arow[4], acc_c[4], brow[2], bcc[2];
#pragma unroll
    for (int q = 0; q < 4; ++q) { int c = tid + 256 * q; arow[q] = c >> 3; acc_c[q] = c & 7; }
#pragma unroll
    for (int q = 0; q < 2; ++q) { int c = tid + 256 * q; brow[q] = c >> 3; bcc[q] = c & 7; }

    uint4 ra[4], rb[2];
    // preload stage 0
#pragma unroll
    for (int q = 0; q < 4; ++q)
        ra[q] = *(const uint4*)(Abase + (size_t)arow[q] * DD + acc_c[q] * 8);
#pragma unroll
    for (int q = 0; q < 2; ++q)
        rb[q] = *(const uint4*)(Bbase + (size_t)brow[q] * DD + bcc[q] * 8);

    for (int s = 0; s < 16; ++s) {
#pragma unroll
        for (int q = 0; q < 4; ++q)
            *(uint4*)(sa_g + arow[q] * 128 + (acc_c[q] ^ (arow[q] & 7)) * 16) = ra[q];
#pragma unroll
        for (int q = 0; q < 2; ++q)
            *(uint4*)(sb_g + brow[q] * 128 + (bcc[q] ^ (brow[q] & 7)) * 16) = rb[q];
        __syncthreads();

        if (s < 15) {  // prefetch next stage (overlaps with MMAs below)
            int kb = (s + 1) * 64;
#pragma unroll
            for (int q = 0; q < 4; ++q)
                ra[q] = *(const uint4*)(Abase + (size_t)arow[q] * DD + kb + acc_c[q] * 8);
#pragma unroll
            for (int q = 0; q < 2; ++q)
                rb[q] = *(const uint4*)(Bbase + (size_t)brow[q] * DD + kb + bcc[q] * 8);
        }

#pragma unroll
        for (int kk = 0; kk < 4; ++kk) {
            uint32_t a0[4], a1[4], bA[4], bB[4];
            {
                int row = a_row0;
                int ch = kk * 2 + a_chunk_sel;
                ldsm4(a0, SA + row * 128 + ((ch ^ (row & 7)) * 16));
                row = a_row0 + 16;
                ldsm4(a1, SA + row * 128 + ((ch ^ (row & 7)) * 16));
            }
            {
                int row = b_row0;
                int ch = kk * 2 + b_chunk_sel;
                ldsm4(bA, SB + row * 128 + ((ch ^ (row & 7)) * 16));
                row = b_row0 + 16;
                ldsm4(bB, SB + row * 128 + ((ch ^ (row & 7)) * 16));
            }
            mma16816(acc[0][0], a0, bA + 0);
            mma16816(acc[0][1], a0, bA + 2);
            mma16816(acc[0][2], a0, bB + 0);
            mma16816(acc[0][3], a0, bB + 2);
            mma16816(acc[1][0], a1, bA + 0);
            mma16816(acc[1][1], a1, bA + 2);
            mma16816(acc[1][2], a1, bB + 0);
            mma16816(acc[1][3], a1, bB + 2);
        }
        __syncthreads();
    }

    // epilogue: scale by inv-norms, exp((cos-1)*10), write g_K
    int mrow_base = mt * 128 + wm * 32 + (lane >> 2);
    int ncol_base = nt * 64 + wn * 32 + (lane & 3) * 2;
    const float* invx = g_inv_nx + b * NN;
    const float* invy = g_inv_ny + b * MM;
#pragma unroll
    for (int mi = 0; mi < 2; ++mi) {
#pragma unroll
        for (int half = 0; half < 2; ++half) {
            int m = mrow_base + mi * 16 + half * 8;
            float invm = invy[m];
            float* out = g_K + ((size_t)(b * MM + m)) * NN;
#pragma unroll
            for (int ni = 0; ni < 4; ++ni) {
                int n = ncol_base + ni * 8;
                float c0 = acc[mi][ni][half * 2 + 0];
                float c1 = acc[mi][ni][half * 2 + 1];
                float s0 = c0 * invm * invx[n];
                float s1 = c1 * invm * invx[n + 1];
                float2 e;
                e.x = __expf((s0 - 1.0f) * 10.0f);
                e.y = __expf((s1 - 1.0f) * 10.0f);
                *(float2*)(out + n) = e;
            }
        }
    }
}

// ---------------- kernel 3: fused persistent Sinkhorn ----------------
// grid = 148 blocks x 512 threads (single resident wave); 5 x (Kv->u, Ktu->v)
__global__ void __launch_bounds__(512) sinkhorn_kernel(const float* __restrict__ mask) {
    __shared__ float usm[MM];
    __shared__ float red2[512];
    __shared__ float red[16];
    const int NBLK = 148;
    int tid = threadIdx.x, blk = blockIdx.x;

    // pre-phase: nu = mask / msum
    if (blk < BB) {
        float mv = (tid < MM) ? mask[blk * MM + tid] : 0.0f;
        float msum = block_sum512(mv, red);
        if (tid < MM) g_nu[blk * MM + tid] = mv / (msum + EPSF);
    }
    grid_bar(NBLK);

    int gw = blk * 16 + (tid >> 5), lane = tid & 31;
    for (int it = 0; it < 5; ++it) {
        // ---- phase A: u = (nu / (K v + eps))^fi  (warp per row) ----
        for (int row = gw; row < BB * MM; row += NBLK * 16) {
            int b = row >> 8;
            const float* Kr = g_K + (size_t)row * NN;
            const float* vb = g_v + b * NN;
            float acc = 0.0f;
            if (it == 0) {
#pragma unroll
                for (int i = 0; i < 18; ++i) acc += Kr[lane + 32 * i];
            } else {
#pragma unroll
                for (int i = 0; i < 18; ++i) {
                    int j = lane + 32 * i;
                    acc += Kr[j] * vb[j];
                }
            }
            acc = warp_sum(acc);
            if (lane == 0) g_u[row] = __powf(g_nu[row] / (acc + EPSF), FI_C);
        }
        grid_bar(NBLK);

        // ---- phase B: v = (mu / (K^T u + eps))^fi  (block per (b, 64-col chunk)) ----
        if (blk < BB * 9) {
            int b = blk / 9, nc = blk % 9;
            if (tid < MM) usm[tid] = g_u[b * MM + tid];
            __syncthreads();
            int nl = tid & 63, mq = tid >> 6;
            const float* Kb = g_K + (size_t)b * MM * NN + nc * 64 + nl;
            float acc = 0.0f;
#pragma unroll 8
            for (int m = mq; m < MM; m += 8)
                acc += Kb[(size_t)m * NN] * usm[m];
            red2[tid] = acc;
            __syncthreads();
            if (mq == 0) {
                float s = 0.0f;
#pragma unroll
                for (int k = 0; k < 8; ++k) s += red2[nl + 64 * k];
                g_v[b * NN + nc * 64 + nl] = __powf(MU_C / (s + EPSF), FI_C);
            }
        }
        grid_bar(NBLK);
    }
}

// ---------------- loss: teacher row (u*K*v normalized) . sum_h log(student) ----
__global__ void __launch_bounds__(256) loss_kernel(const float* __restrict__ student,
                                                   const float* __restrict__ mask) {
    __shared__ float psm[NN];
    __shared__ float red[8];
    int blk = blockIdx.x, tid = threadIdx.x;
    int b = blk >> 8, m = blk & 255;
    float u = g_u[blk];
    float mk = mask[b * MM + m];
    const float* Kr = g_K + (size_t)blk * NN;
    const float* vb = g_v + b * NN;
    float rs = 0.0f;
    for (int j = tid; j < NN; j += 256) {
        float p = u * Kr[j] * vb[j];
        psm[j] = p;
        rs += p;
    }
    float rowsum = block_sum256(rs, red);  // also publishes psm
    float acc = 0.0f;
    const float* sbase = student + ((size_t)(b * HH) * MM + m) * NN;
#pragma unroll
    for (int jj = 0; jj < 3; ++jj) {
        int j = tid + jj * 256;
        if (j < NN) {
            float p = psm[j];
            float lg[HH];
#pragma unroll
            for (int h = 0; h < HH; ++h)
                lg[h] = __ldcs(sbase + (size_t)h * MM * NN + j);
#pragma unroll
            for (int h = 0; h < HH; ++h)
                acc += p * __logf(lg[h] + EPSF);
        }
    }
    float tot = block_sum256(acc, red);
    if (tid == 0) g_partial[blk] = -(tot / (rowsum + EPSF)) * mk;
}

// ---------------- final reduce ----------------
__global__ void __launch_bounds__(256) reduce_kernel(float* __restrict__ out) {
    __shared__ float red[8];
    int tid = threadIdx.x;
    float s = 0.0f;
    for (int i = tid; i < BB * MM; i += 256) s += g_partial[i];
    float t = block_sum256(s, red);
    if (tid == 0) out[0] = t * (1.0f / (float)(BB * HH * MM));
}

// ---------------- launch ----------------
extern "C" void kernel_launch(void* const* d_in, const int* in_sizes, int n_in,
                              void* d_out, int out_size) {
    const float *student = nullptr, *visual = nullptr, *text = nullptr, *mask = nullptr;
    for (int i = 0; i < n_in; ++i) {
        long sz = in_sizes[i];
        if (sz == (long)BB * HH * MM * NN) student = (const float*)d_in[i];
        else if (sz == (long)BB * NN * DD) visual = (const float*)d_in[i];
        else if (sz == (long)BB * MM * DD) text = (const float*)d_in[i];
        else if (sz == (long)BB * MM) mask = (const float*)d_in[i];
    }
    float* out = (float*)d_out;

    prep_kernel<<<(BB * NN + BB * MM) / 8, 256>>>(visual, text);
    gemm_expK_kernel<<<dim3(NN / 64, MM / 128, BB), 256>>>();
    sinkhorn_kernel<<<148, 512>>>(mask);
    loss_kernel<<<BB * MM, 256>>>(student, mask);
    reduce_kernel<<<1, 256>>>(out);
}

// round 4
// speedup vs baseline: 1.4980x; 1.0010x over previous
#include <cuda_runtime.h>
#include <cuda_bf16.h>
#include <cstdint>

// Problem constants: B=16, H=16, M=256, N=576, D=1024
#define BB 16
#define HH 16
#define MM 256
#define NN 576
#define DD 1024

#define EPSF 1e-8f
#define MU_C (1.0f / 576.0f)
#define FI_C (1.0f / 1.1f)

// ---------------- device scratch ----------------
__device__ __nv_bfloat16 g_xb[BB * NN * DD];   // visual feats bf16 (raw)
__device__ __nv_bfloat16 g_yb[BB * MM * DD];   // text feats bf16 (raw)
__device__ float g_inv_nx[BB * NN];
__device__ float g_inv_ny[BB * MM];
__device__ float g_K[BB * MM * NN];            // exp(-cost/eps)
__device__ float g_u[BB * MM];                 // Sinkhorn u
__device__ float g_v[BB * NN];                 // Sinkhorn v
__device__ float g_nu[BB * MM];
__device__ float g_partial[BB * MM];
__device__ unsigned g_bar_cnt;
__device__ volatile unsigned g_bar_gen;

// ---------------- helpers ----------------
__device__ __forceinline__ float warp_sum(float v) {
#pragma unroll
    for (int o = 16; o; o >>= 1) v += __shfl_xor_sync(0xffffffffu, v, o);
    return v;
}

__device__ __forceinline__ float block_sum256(float v, volatile float* red) {
    int tid = threadIdx.x;
    float w = warp_sum(v);
    if ((tid & 31) == 0) red[tid >> 5] = w;
    __syncthreads();
    if (tid < 32) {
        float r = (tid < 8) ? red[tid] : 0.0f;
        r = warp_sum(r);
        if (tid == 0) red[0] = r;
    }
    __syncthreads();
    float out = red[0];
    __syncthreads();
    return out;
}

__device__ __forceinline__ float block_sum512(float v, volatile float* red) {
    int tid = threadIdx.x;
    float w = warp_sum(v);
    if ((tid & 31) == 0) red[tid >> 5] = w;
    __syncthreads();
    if (tid < 32) {
        float r = (tid < 16) ? red[tid] : 0.0f;
        r = warp_sum(r);
        if (tid == 0) red[0] = r;
    }
    __syncthreads();
    float out = red[0];
    __syncthreads();
    return out;
}

// grid-wide barrier: grid must be a single resident wave (grid <= 148)
__device__ __forceinline__ void grid_bar(int nblk) {
    __threadfence();
    __syncthreads();
    if (threadIdx.x == 0) {
        unsigned gen = g_bar_gen;
        if (atomicAdd(&g_bar_cnt, 1u) == (unsigned)(nblk - 1)) {
            g_bar_cnt = 0;
            __threadfence();
            g_bar_gen = gen + 1;
        } else {
            while (g_bar_gen == gen) {}
        }
        __threadfence();
    }
    __syncthreads();
}

__device__ __forceinline__ void ldsm4(uint32_t* r, uint32_t addr) {
    asm volatile("ldmatrix.sync.aligned.m8n8.x4.shared.b16 {%0,%1,%2,%3}, [%4];"
                 : "=r"(r[0]), "=r"(r[1]), "=r"(r[2]), "=r"(r[3]) : "r"(addr));
}

__device__ __forceinline__ void mma16816(float* c, const uint32_t* a, const uint32_t* b) {
    asm volatile(
        "mma.sync.aligned.m16n8k16.row.col.f32.bf16.bf16.f32 "
        "{%0,%1,%2,%3}, {%4,%5,%6,%7}, {%8,%9}, {%0,%1,%2,%3};"
        : "+f"(c[0]), "+f"(c[1]), "+f"(c[2]), "+f"(c[3])
        : "r"(a[0]), "r"(a[1]), "r"(a[2]), "r"(a[3]), "r"(b[0]), "r"(b[1]));
}

__device__ __forceinline__ void cp16(uint32_t dst, const void* src) {
    asm volatile("cp.async.cg.shared.global [%0], [%1], 16;" :: "r"(dst), "l"(src));
}

// ---------------- kernel 1: norms + bf16 conversion ----------------
__global__ void __launch_bounds__(256) prep_kernel(const float* __restrict__ visual,
                                                   const float* __restrict__ text) {
    int warp = blockIdx.x * 8 + (threadIdx.x >> 5);
    int lane = threadIdx.x & 31;
    const int VROWS = BB * NN;
    const float* src;
    __nv_bfloat16* dst;
    float* invp;
    if (warp < VROWS) {
        src = visual + (size_t)warp * DD;
        dst = g_xb + (size_t)warp * DD;
        invp = g_inv_nx + warp;
    } else {
        int r = warp - VROWS;
        src = text + (size_t)r * DD;
        dst = g_yb + (size_t)r * DD;
        invp = g_inv_ny + r;
    }
    const float4* s4 = (const float4*)src;
    uint2* d2 = (uint2*)dst;
    float ss = 0.0f;
#pragma unroll
    for (int i = 0; i < 8; ++i) {
        float4 v = __ldcs(&s4[lane + 32 * i]);
        ss += v.x * v.x + v.y * v.y + v.z * v.z + v.w * v.w;
        uint32_t lo = (uint32_t)__bfloat16_as_ushort(__float2bfloat16_rn(v.x))
                    | ((uint32_t)__bfloat16_as_ushort(__float2bfloat16_rn(v.y)) << 16);
        uint32_t hi = (uint32_t)__bfloat16_as_ushort(__float2bfloat16_rn(v.z))
                    | ((uint32_t)__bfloat16_as_ushort(__float2bfloat16_rn(v.w)) << 16);
        d2[lane + 32 * i] = make_uint2(lo, hi);
    }
    ss = warp_sum(ss);
    if (lane == 0) *invp = rsqrtf(ss + 1e-12f);
}

// ---------------- kernel 2: HMMA bf16 GEMM, cp.async double-buffered ----------
// grid: (nt=9, mt=2, b=16); block 256 = 8 warps (4 x 2).
__global__ void __launch_bounds__(256) gemm_expK_kernel() {
    __shared__ __align__(16) char sa_g[2][128 * 128];
    __shared__ __align__(16) char sb_g[2][64 * 128];
    uint32_t SA = (uint32_t)__cvta_generic_to_shared(&sa_g[0][0]);
    uint32_t SB = (uint32_t)__cvta_generic_to_shared(&sb_g[0][0]);

    int tid = threadIdx.x, wid = tid >> 5, lane = tid & 31;
    int nt = blockIdx.x, mt = blockIdx.y, b = blockIdx.z;
    int wm = wid & 3, wn = wid >> 2;

    const __nv_bfloat16* Abase = g_yb + ((size_t)(b * MM + mt * 128)) * DD;
    const __nv_bfloat16* Bbase = g_xb + ((size_t)(b * NN + nt * 64)) * DD;

    float acc[2][4][4];
#pragma unroll
    for (int i = 0; i < 2; ++i)
#pragma unroll
        for (int j = 0; j < 4; ++j)
#pragma unroll
            for (int k = 0; k < 4; ++k) acc[i][j][k] = 0.0f;

    int a_row0 = wm * 32 + ((lane >> 3) & 1) * 8 + (lane & 7);
    int a_chunk_sel = (lane >> 4);
    int b_row0 = wn * 32 + (lane >> 4) * 8 + (lane & 7);
    int b_chunk_sel = ((lane >> 3) & 1);

    // per-thread staging coords
    int arow[4], acol[4], brow[2], bcol[2];
    uint32_t adst[4], bdst[2];
#pragma unroll
    for (int q = 0; q < 4; ++q) {
        int c = tid + 256 * q;
        arow[q] = c >> 3; acol[q] = c & 7;
        adst[q] = SA + arow[q] * 128 + ((acol[q] ^ (arow[q] & 7)) * 16);
    }
#pragma unroll
    for (int q = 0; q < 2; ++q) {
        int c = tid + 256 * q;
        brow[q] = c >> 3; bcol[q] = c & 7;
        bdst[q] = SB + brow[q] * 128 + ((bcol[q] ^ (brow[q] & 7)) * 16);
    }

    // issue stage 0
#pragma unroll
    for (int q = 0; q < 4; ++q)
        cp16(adst[q], Abase + (size_t)arow[q] * DD + acol[q] * 8);
#pragma unroll
    for (int q = 0; q < 2; ++q)
        cp16(bdst[q], Bbase + (size_t)brow[q] * DD + bcol[q] * 8);
    asm volatile("cp.async.commit_group;" ::: "memory");

    for (int s = 0; s < 16; ++s) {
        asm volatile("cp.async.wait_group 0;" ::: "memory");
        __syncthreads();
        if (s < 15) {  // issue next stage into the other buffer (overlaps MMAs)
            int kb = (s + 1) * 64;
            uint32_t boff = ((s + 1) & 1) ? 16384u : 0u;
            uint32_t boffB = ((s + 1) & 1) ? 8192u : 0u;
#pragma unroll
            for (int q = 0; q < 4; ++q)
                cp16(adst[q] + boff, Abase + (size_t)arow[q] * DD + kb + acol[q] * 8);
#pragma unroll
            for (int q = 0; q < 2; ++q)
                cp16(bdst[q] + boffB, Bbase + (size_t)brow[q] * DD + kb + bcol[q] * 8);
            asm volatile("cp.async.commit_group;" ::: "memory");
        }

        uint32_t SAc = SA + ((s & 1) ? 16384u : 0u);
        uint32_t SBc = SB + ((s & 1) ? 8192u : 0u);
#pragma unroll
        for (int kk = 0; kk < 4; ++kk) {
            uint32_t a0[4], a1[4], bA[4], bB[4];
            {
                int row = a_row0;
                int ch = kk * 2 + a_chunk_sel;
                ldsm4(a0, SAc + row * 128 + ((ch ^ (row & 7)) * 16));
                row = a_row0 + 16;
                ldsm4(a1, SAc + row * 128 + ((ch ^ (row & 7)) * 16));
            }
            {
                int row = b_row0;
                int ch = kk * 2 + b_chunk_sel;
                ldsm4(bA, SBc + row * 128 + ((ch ^ (row & 7)) * 16));
                row = b_row0 + 16;
                ldsm4(bB, SBc + row * 128 + ((ch ^ (row & 7)) * 16));
            }
            mma16816(acc[0][0], a0, bA + 0);
            mma16816(acc[0][1], a0, bA + 2);
            mma16816(acc[0][2], a0, bB + 0);
            mma16816(acc[0][3], a0, bB + 2);
            mma16816(acc[1][0], a1, bA + 0);
            mma16816(acc[1][1], a1, bA + 2);
            mma16816(acc[1][2], a1, bB + 0);
            mma16816(acc[1][3], a1, bB + 2);
        }
    }

    // epilogue: scale by inv-norms, exp((cos-1)*10), write g_K
    int mrow_base = mt * 128 + wm * 32 + (lane >> 2);
    int ncol_base = nt * 64 + wn * 32 + (lane & 3) * 2;
    const float* invx = g_inv_nx + b * NN;
    const float* invy = g_inv_ny + b * MM;
#pragma unroll
    for (int mi = 0; mi < 2; ++mi) {
#pragma unroll
        for (int half = 0; half < 2; ++half) {
            int m = mrow_base + mi * 16 + half * 8;
            float invm = invy[m];
            float* out = g_K + ((size_t)(b * MM + m)) * NN;
#pragma unroll
            for (int ni = 0; ni < 4; ++ni) {
                int n = ncol_base + ni * 8;
                float c0 = acc[mi][ni][half * 2 + 0];
                float c1 = acc[mi][ni][half * 2 + 1];
                float s0 = c0 * invm * invx[n];
                float s1 = c1 * invm * invx[n + 1];
                float2 e;
                e.x = __expf((s0 - 1.0f) * 10.0f);
                e.y = __expf((s1 - 1.0f) * 10.0f);
                *(float2*)(out + n) = e;
            }
        }
    }
}

// ---------------- kernel 3: fused persistent Sinkhorn ----------------
// grid = 148 blocks x 512 threads (single resident wave); 5 x (Kv->u, Ktu->v)
__global__ void __launch_bounds__(512) sinkhorn_kernel(const float* __restrict__ mask) {
    __shared__ float usm[MM];
    __shared__ float red2[512];
    __shared__ float red[16];
    const int NBLK = 148;
    int tid = threadIdx.x, blk = blockIdx.x;

    // pre-phase: nu = mask / msum
    if (blk < BB) {
        float mv = (tid < MM) ? mask[blk * MM + tid] : 0.0f;
        float msum = block_sum512(mv, red);
        if (tid < MM) g_nu[blk * MM + tid] = mv / (msum + EPSF);
    }
    grid_bar(NBLK);

    int gw = blk * 16 + (tid >> 5), lane = tid & 31;
    for (int it = 0; it < 5; ++it) {
        // ---- phase A: u = (nu / (K v + eps))^fi  (warp per row) ----
        for (int row = gw; row < BB * MM; row += NBLK * 16) {
            int b = row >> 8;
            const float* Kr = g_K + (size_t)row * NN;
            const float* vb = g_v + b * NN;
            float acc = 0.0f;
            if (it == 0) {
#pragma unroll
                for (int i = 0; i < 18; ++i) acc += Kr[lane + 32 * i];
            } else {
#pragma unroll
                for (int i = 0; i < 18; ++i) {
                    int j = lane + 32 * i;
                    acc += Kr[j] * vb[j];
                }
            }
            acc = warp_sum(acc);
            if (lane == 0) g_u[row] = __powf(g_nu[row] / (acc + EPSF), FI_C);
        }
        grid_bar(NBLK);

        // ---- phase B: v = (mu / (K^T u + eps))^fi  (block per (b, 64-col chunk)) ----
        if (blk < BB * 9) {
            int b = blk / 9, nc = blk % 9;
            if (tid < MM) usm[tid] = g_u[b * MM + tid];
            __syncthreads();
            int nl = tid & 63, mq = tid >> 6;
            const float* Kb = g_K + (size_t)b * MM * NN + nc * 64 + nl;
            float acc = 0.0f;
#pragma unroll 8
            for (int m = mq; m < MM; m += 8)
                acc += Kb[(size_t)m * NN] * usm[m];
            red2[tid] = acc;
            __syncthreads();
            if (mq == 0) {
                float s = 0.0f;
#pragma unroll
                for (int k = 0; k < 8; ++k) s += red2[nl + 64 * k];
                g_v[b * NN + nc * 64 + nl] = __powf(MU_C / (s + EPSF), FI_C);
            }
        }
        grid_bar(NBLK);
    }
}

// ---------------- loss: teacher row (u*K*v normalized) . sum_h log(student) ----
__global__ void __launch_bounds__(256) loss_kernel(const float* __restrict__ student,
                                                   const float* __restrict__ mask) {
    __shared__ __align__(16) float psm[NN];
    __shared__ float red[8];
    int blk = blockIdx.x, tid = threadIdx.x;
    int b = blk >> 8, m = blk & 255;
    float u = g_u[blk];
    float mk = mask[b * MM + m];
    const float* Kr = g_K + (size_t)blk * NN;
    const float* vb = g_v + b * NN;
    float rs = 0.0f;
    for (int j = tid; j < NN; j += 256) {
        float p = u * Kr[j] * vb[j];
        psm[j] = p;
        rs += p;
    }
    float rowsum = block_sum256(rs, red);  // also publishes psm
    // flattened (head, j/4) items: 16 * 144 = 2304 = 9 * 256
    float acc = 0.0f;
    const float4* s4 = (const float4*)student;
    size_t rbase = (size_t)(b * HH) * MM + m;  // row index of head 0
#pragma unroll
    for (int k = 0; k < 9; ++k) {
        int item = tid + 256 * k;
        int h = item / 144;
        int jv = item - h * 144;
        float4 s = __ldcs(s4 + (rbase + (size_t)h * MM) * 144 + jv);
        float4 p = *(const float4*)(psm + jv * 4);
        acc += p.x * __logf(s.x + EPSF) + p.y * __logf(s.y + EPSF)
             + p.z * __logf(s.z + EPSF) + p.w * __logf(s.w + EPSF);
    }
    float tot = block_sum256(acc, red);
    if (tid == 0) g_partial[blk] = -(tot / (rowsum + EPSF)) * mk;
}

// ---------------- final reduce ----------------
__global__ void __launch_bounds__(256) reduce_kernel(float* __restrict__ out) {
    __shared__ float red[8];
    int tid = threadIdx.x;
    float s = 0.0f;
    for (int i = tid; i < BB * MM; i += 256) s += g_partial[i];
    float t = block_sum256(s, red);
    if (tid == 0) out[0] = t * (1.0f / (float)(BB * HH * MM));
}

// ---------------- launch ----------------
extern "C" void kernel_launch(void* const* d_in, const int* in_sizes, int n_in,
                              void* d_out, int out_size) {
    const float *student = nullptr, *visual = nullptr, *text = nullptr, *mask = nullptr;
    for (int i = 0; i < n_in; ++i) {
        long sz = in_sizes[i];
        if (sz == (long)BB * HH * MM * NN) student = (const float*)d_in[i];
        else if (sz == (long)BB * NN * DD) visual = (const float*)d_in[i];
        else if (sz == (long)BB * MM * DD) text = (const float*)d_in[i];
        else if (sz == (long)BB * MM) mask = (const float*)d_in[i];
    }
    float* out = (float*)d_out;

    prep_kernel<<<(BB * NN + BB * MM) / 8, 256>>>(visual, text);
    gemm_expK_kernel<<<dim3(NN / 64, MM / 128, BB), 256>>>();
    sinkhorn_kernel<<<148, 512>>>(mask);
    loss_kernel<<<BB * MM, 256>>>(student, mask);
    reduce_kernel<<<1, 256>>>(out);
}

// round 5
// speedup vs baseline: 1.5738x; 1.0506x over previous
#include <cuda_runtime.h>
#include <cuda_bf16.h>
#include <cstdint>

// Problem constants: B=16, H=16, M=256, N=576, D=1024
#define BB 16
#define HH 16
#define MM 256
#define NN 576
#define DD 1024

#define EPSF 1e-8f
#define MU_C (1.0f / 576.0f)
#define FI_C (1.0f / 1.1f)

// ---------------- device scratch ----------------
__device__ __nv_bfloat16 g_xb[BB * NN * DD];   // visual feats bf16 (raw)
__device__ __nv_bfloat16 g_yb[BB * MM * DD];   // text feats bf16 (raw)
__device__ float g_inv_nx[BB * NN];
__device__ float g_inv_ny[BB * MM];
__device__ float g_K[BB * MM * NN];            // exp(-cost/eps)
__device__ float g_u[BB * MM];                 // Sinkhorn u
__device__ float g_v[BB * NN];                 // Sinkhorn v
__device__ float g_vacc[BB * NN];              // Ktu accumulator
__device__ float g_nu[BB * MM];
__device__ float g_partial[BB * MM * 2];

// ---------------- helpers ----------------
__device__ __forceinline__ float warp_sum(float v) {
#pragma unroll
    for (int o = 16; o; o >>= 1) v += __shfl_xor_sync(0xffffffffu, v, o);
    return v;
}

__device__ __forceinline__ float block_sum256(float v, volatile float* red) {
    int tid = threadIdx.x;
    float w = warp_sum(v);
    if ((tid & 31) == 0) red[tid >> 5] = w;
    __syncthreads();
    if (tid < 32) {
        float r = (tid < 8) ? red[tid] : 0.0f;
        r = warp_sum(r);
        if (tid == 0) red[0] = r;
    }
    __syncthreads();
    float out = red[0];
    __syncthreads();
    return out;
}

__device__ __forceinline__ void cluster_sync() {
    asm volatile("barrier.cluster.arrive.aligned;" ::: "memory");
    asm volatile("barrier.cluster.wait.aligned;" ::: "memory");
}

__device__ __forceinline__ void ldsm4(uint32_t* r, uint32_t addr) {
    asm volatile("ldmatrix.sync.aligned.m8n8.x4.shared.b16 {%0,%1,%2,%3}, [%4];"
                 : "=r"(r[0]), "=r"(r[1]), "=r"(r[2]), "=r"(r[3]) : "r"(addr));
}

__device__ __forceinline__ void mma16816(float* c, const uint32_t* a, const uint32_t* b) {
    asm volatile(
        "mma.sync.aligned.m16n8k16.row.col.f32.bf16.bf16.f32 "
        "{%0,%1,%2,%3}, {%4,%5,%6,%7}, {%8,%9}, {%0,%1,%2,%3};"
        : "+f"(c[0]), "+f"(c[1]), "+f"(c[2]), "+f"(c[3])
        : "r"(a[0]), "r"(a[1]), "r"(a[2]), "r"(a[3]), "r"(b[0]), "r"(b[1]));
}

__device__ __forceinline__ void cp16(uint32_t dst, const void* src) {
    asm volatile("cp.async.cg.shared.global [%0], [%1], 16;" :: "r"(dst), "l"(src));
}

// ---------------- kernel 1: norms + bf16 conversion ----------------
__global__ void __launch_bounds__(256) prep_kernel(const float* __restrict__ visual,
                                                   const float* __restrict__ text) {
    int warp = blockIdx.x * 8 + (threadIdx.x >> 5);
    int lane = threadIdx.x & 31;
    const int VROWS = BB * NN;
    const float* src;
    __nv_bfloat16* dst;
    float* invp;
    if (warp < VROWS) {
        src = visual + (size_t)warp * DD;
        dst = g_xb + (size_t)warp * DD;
        invp = g_inv_nx + warp;
    } else {
        int r = warp - VROWS;
        src = text + (size_t)r * DD;
        dst = g_yb + (size_t)r * DD;
        invp = g_inv_ny + r;
    }
    const float4* s4 = (const float4*)src;
    uint2* d2 = (uint2*)dst;
    float ss = 0.0f;
#pragma unroll
    for (int i = 0; i < 8; ++i) {
        float4 v = __ldcs(&s4[lane + 32 * i]);
        ss += v.x * v.x + v.y * v.y + v.z * v.z + v.w * v.w;
        uint32_t lo = (uint32_t)__bfloat16_as_ushort(__float2bfloat16_rn(v.x))
                    | ((uint32_t)__bfloat16_as_ushort(__float2bfloat16_rn(v.y)) << 16);
        uint32_t hi = (uint32_t)__bfloat16_as_ushort(__float2bfloat16_rn(v.z))
                    | ((uint32_t)__bfloat16_as_ushort(__float2bfloat16_rn(v.w)) << 16);
        d2[lane + 32 * i] = make_uint2(lo, hi);
    }
    ss = warp_sum(ss);
    if (lane == 0) *invp = rsqrtf(ss + 1e-12f);
}

// ---------------- kernel 2: HMMA bf16 GEMM, cp.async double-buffered ----------
// grid: (nt=9, mt=2, b=16); block 256 = 8 warps (4 x 2).
__global__ void __launch_bounds__(256) gemm_expK_kernel() {
    __shared__ __align__(16) char sa_g[2][128 * 128];
    __shared__ __align__(16) char sb_g[2][64 * 128];
    uint32_t SA = (uint32_t)__cvta_generic_to_shared(&sa_g[0][0]);
    uint32_t SB = (uint32_t)__cvta_generic_to_shared(&sb_g[0][0]);

    int tid = threadIdx.x, wid = tid >> 5, lane = tid & 31;
    int nt = blockIdx.x, mt = blockIdx.y, b = blockIdx.z;
    int wm = wid & 3, wn = wid >> 2;

    const __nv_bfloat16* Abase = g_yb + ((size_t)(b * MM + mt * 128)) * DD;
    const __nv_bfloat16* Bbase = g_xb + ((size_t)(b * NN + nt * 64)) * DD;

    float acc[2][4][4];
#pragma unroll
    for (int i = 0; i < 2; ++i)
#pragma unroll
        for (int j = 0; j < 4; ++j)
#pragma unroll
            for (int k = 0; k < 4; ++k) acc[i][j][k] = 0.0f;

    int a_row0 = wm * 32 + ((lane >> 3) & 1) * 8 + (lane & 7);
    int a_chunk_sel = (lane >> 4);
    int b_row0 = wn * 32 + (lane >> 4) * 8 + (lane & 7);
    int b_chunk_sel = ((lane >> 3) & 1);

    int arow[4], acol[4], brow[2], bcol[2];
    uint32_t adst[4], bdst[2];
#pragma unroll
    for (int q = 0; q < 4; ++q) {
        int c = tid + 256 * q;
        arow[q] = c >> 3; acol[q] = c & 7;
        adst[q] = SA + arow[q] * 128 + ((acol[q] ^ (arow[q] & 7)) * 16);
    }
#pragma unroll
    for (int q = 0; q < 2; ++q) {
        int c = tid + 256 * q;
        brow[q] = c >> 3; bcol[q] = c & 7;
        bdst[q] = SB + brow[q] * 128 + ((bcol[q] ^ (brow[q] & 7)) * 16);
    }

    // issue stage 0
#pragma unroll
    for (int q = 0; q < 4; ++q)
        cp16(adst[q], Abase + (size_t)arow[q] * DD + acol[q] * 8);
#pragma unroll
    for (int q = 0; q < 2; ++q)
        cp16(bdst[q], Bbase + (size_t)brow[q] * DD + bcol[q] * 8);
    asm volatile("cp.async.commit_group;" ::: "memory");

    for (int s = 0; s < 16; ++s) {
        asm volatile("cp.async.wait_group 0;" ::: "memory");
        __syncthreads();
        if (s < 15) {
            int kb = (s + 1) * 64;
            uint32_t boff = ((s + 1) & 1) ? 16384u : 0u;
            uint32_t boffB = ((s + 1) & 1) ? 8192u : 0u;
#pragma unroll
            for (int q = 0; q < 4; ++q)
                cp16(adst[q] + boff, Abase + (size_t)arow[q] * DD + kb + acol[q] * 8);
#pragma unroll
            for (int q = 0; q < 2; ++q)
                cp16(bdst[q] + boffB, Bbase + (size_t)brow[q] * DD + kb + bcol[q] * 8);
            asm volatile("cp.async.commit_group;" ::: "memory");
        }

        uint32_t SAc = SA + ((s & 1) ? 16384u : 0u);
        uint32_t SBc = SB + ((s & 1) ? 8192u : 0u);
#pragma unroll
        for (int kk = 0; kk < 4; ++kk) {
            uint32_t a0[4], a1[4], bA[4], bB[4];
            {
                int row = a_row0;
                int ch = kk * 2 + a_chunk_sel;
                ldsm4(a0, SAc + row * 128 + ((ch ^ (row & 7)) * 16));
                row = a_row0 + 16;
                ldsm4(a1, SAc + row * 128 + ((ch ^ (row & 7)) * 16));
            }
            {
                int row = b_row0;
                int ch = kk * 2 + b_chunk_sel;
                ldsm4(bA, SBc + row * 128 + ((ch ^ (row & 7)) * 16));
                row = b_row0 + 16;
                ldsm4(bB, SBc + row * 128 + ((ch ^ (row & 7)) * 16));
            }
            mma16816(acc[0][0], a0, bA + 0);
            mma16816(acc[0][1], a0, bA + 2);
            mma16816(acc[0][2], a0, bB + 0);
            mma16816(acc[0][3], a0, bB + 2);
            mma16816(acc[1][0], a1, bA + 0);
            mma16816(acc[1][1], a1, bA + 2);
            mma16816(acc[1][2], a1, bB + 0);
            mma16816(acc[1][3], a1, bB + 2);
        }
    }

    // epilogue: scale by inv-norms, exp((cos-1)*10), write g_K
    int mrow_base = mt * 128 + wm * 32 + (lane >> 2);
    int ncol_base = nt * 64 + wn * 32 + (lane & 3) * 2;
    const float* invx = g_inv_nx + b * NN;
    const float* invy = g_inv_ny + b * MM;
#pragma unroll
    for (int mi = 0; mi < 2; ++mi) {
#pragma unroll
        for (int half = 0; half < 2; ++half) {
            int m = mrow_base + mi * 16 + half * 8;
            float invm = invy[m];
            float* out = g_K + ((size_t)(b * MM + m)) * NN;
#pragma unroll
            for (int ni = 0; ni < 4; ++ni) {
                int n = ncol_base + ni * 8;
                float c0 = acc[mi][ni][half * 2 + 0];
                float c1 = acc[mi][ni][half * 2 + 1];
                float s0 = c0 * invm * invx[n];
                float s1 = c1 * invm * invx[n + 1];
                float2 e;
                e.x = __expf((s0 - 1.0f) * 10.0f);
                e.y = __expf((s1 - 1.0f) * 10.0f);
                *(float2*)(out + n) = e;
            }
        }
    }
}

// ---------------- kernel 3: Sinkhorn, one 8-CTA cluster per batch ----------------
// grid = 128 CTAs (16 clusters x 8) x 256 threads.
// Each CTA owns 32 K-rows of its batch: phase A (row dot) and phase B
// (partial column sums, row-major) both touch only those rows -> L1-resident.
__global__ void __cluster_dims__(8, 1, 1) __launch_bounds__(256)
sinkhorn_kernel(const float* __restrict__ mask) {
    __shared__ float vsm[NN];
    __shared__ float usm[32];
    __shared__ float red[8];
    int tid = threadIdx.x;
    int b = blockIdx.x >> 3;
    int rank = blockIdx.x & 7;
    int wid = tid >> 5, lane = tid & 31;

    // pre-phase: rank 0 computes nu; all ranks init v=1, vacc=0 for their cols
    if (rank == 0) {
        float mv = mask[b * MM + tid];
        float msum = block_sum256(mv, red);
        g_nu[b * MM + tid] = mv / (msum + EPSF);
    }
    if (tid < 72) {
        int col = rank * 72 + tid;
        g_v[b * NN + col] = 1.0f;
        g_vacc[b * NN + col] = 0.0f;
    }
    __threadfence();
    cluster_sync();

    const int row0 = rank * 32;                      // this CTA's 32 rows
    const float* Kbase = g_K + ((size_t)(b * MM + row0)) * NN;

    for (int it = 0; it < 5; ++it) {
        // ---- phase A: u = (nu / (K v + eps))^fi for our 32 rows ----
        for (int j = tid; j < NN; j += 256) vsm[j] = __ldcg(g_v + b * NN + j);
        __syncthreads();
#pragma unroll
        for (int r = 0; r < 4; ++r) {
            int rl = wid * 4 + r;                    // local row 0..31
            const float* Kr = Kbase + (size_t)rl * NN;
            float acc = 0.0f;
#pragma unroll
            for (int i = 0; i < 18; ++i) {
                int j = lane + 32 * i;
                acc += Kr[j] * vsm[j];
            }
            acc = warp_sum(acc);
            if (lane == 0) {
                int g = b * MM + row0 + rl;
                g_u[g] = __powf(__ldcg(g_nu + g) / (acc + EPSF), FI_C);
            }
        }
        __threadfence();
        cluster_sync();

        // ---- phase B: partial Ktu over our 32 rows (row-major, coalesced) ----
        if (tid < 32) usm[tid] = __ldcg(g_u + b * MM + row0 + tid);
        __syncthreads();
        float a0 = 0.0f, a1 = 0.0f, a2 = 0.0f;
#pragma unroll 4
        for (int r = 0; r < 32; ++r) {
            const float* Kr = Kbase + (size_t)r * NN;
            float ur = usm[r];
            a0 += Kr[tid] * ur;
            a1 += Kr[tid + 256] * ur;
            if (tid < 64) a2 += Kr[tid + 512] * ur;
        }
        atomicAdd(g_vacc + b * NN + tid, a0);
        atomicAdd(g_vacc + b * NN + tid + 256, a1);
        if (tid < 64) atomicAdd(g_vacc + b * NN + tid + 512, a2);
        __threadfence();
        cluster_sync();

        // ---- v = (mu / (vacc + eps))^fi; reset vacc ----
        if (tid < 72) {
            int col = b * NN + rank * 72 + tid;
            float s = __ldcg(g_vacc + col);
            g_v[col] = __powf(MU_C / (s + EPSF), FI_C);
            g_vacc[col] = 0.0f;
        }
        __threadfence();
        cluster_sync();
    }
}

// ---------------- loss: teacher row . sum_h log(student); 2 blocks/row -------
__global__ void __launch_bounds__(256) loss_kernel(const float* __restrict__ student,
                                                   const float* __restrict__ mask) {
    __shared__ float psm[NN];
    __shared__ float red[8];
    int blk = blockIdx.x, hb = blockIdx.y, tid = threadIdx.x;
    int b = blk >> 8, m = blk & 255;
    float u = g_u[blk];
    float mk = mask[b * MM + m];
    const float* Kr = g_K + (size_t)blk * NN;
    const float* vb = g_v + b * NN;
    float rs = 0.0f;
    for (int j = tid; j < NN; j += 256) {
        float p = u * Kr[j] * vb[j];
        psm[j] = p;
        rs += p;
    }
    float rowsum = block_sum256(rs, red);  // also publishes psm
    float acc = 0.0f;
    const float* sbase = student + ((size_t)(b * HH + hb * 8) * MM + m) * NN;
#pragma unroll
    for (int jj = 0; jj < 3; ++jj) {
        int j = tid + jj * 256;
        if (j < NN) {
            float p = psm[j];
            float lg[8];
#pragma unroll
            for (int h = 0; h < 8; ++h)
                lg[h] = __ldcs(sbase + (size_t)h * MM * NN + j);
#pragma unroll
            for (int h = 0; h < 8; ++h)
                acc += p * __logf(lg[h] + EPSF);
        }
    }
    float tot = block_sum256(acc, red);
    if (tid == 0) g_partial[blk * 2 + hb] = -(tot / (rowsum + EPSF)) * mk;
}

// ---------------- final reduce ----------------
__global__ void __launch_bounds__(256) reduce_kernel(float* __restrict__ out) {
    __shared__ float red[8];
    int tid = threadIdx.x;
    float s = 0.0f;
    for (int i = tid; i < BB * MM * 2; i += 256) s += g_partial[i];
    float t = block_sum256(s, red);
    if (tid == 0) out[0] = t * (1.0f / (float)(BB * HH * MM));
}

// ---------------- launch ----------------
extern "C" void kernel_launch(void* const* d_in, const int* in_sizes, int n_in,
                              void* d_out, int out_size) {
    const float *student = nullptr, *visual = nullptr, *text = nullptr, *mask = nullptr;
    for (int i = 0; i < n_in; ++i) {
        long sz = in_sizes[i];
        if (sz == (long)BB * HH * MM * NN) student = (const float*)d_in[i];
        else if (sz == (long)BB * NN * DD) visual = (const float*)d_in[i];
        else if (sz == (long)BB * MM * DD) text = (const float*)d_in[i];
        else if (sz == (long)BB * MM) mask = (const float*)d_in[i];
    }
    float* out = (float*)d_out;

    prep_kernel<<<(BB * NN + BB * MM) / 8, 256>>>(visual, text);
    gemm_expK_kernel<<<dim3(NN / 64, MM / 128, BB), 256>>>();
    sinkhorn_kernel<<<128, 256>>>(mask);
    loss_kernel<<<dim3(BB * MM, 2), 256>>>(student, mask);
    reduce_kernel<<<1, 256>>>(out);
}

// round 6
// speedup vs baseline: 1.6878x; 1.0724x over previous
#include <cuda_runtime.h>
#include <cuda_bf16.h>
#include <cstdint>

// Problem constants: B=16, H=16, M=256, N=576, D=1024
#define BB 16
#define HH 16
#define MM 256
#define NN 576
#define DD 1024

#define EPSF 1e-8f
#define MU_C (1.0f / 576.0f)
#define FI_C (1.0f / 1.1f)

// ---------------- device scratch ----------------
__device__ __nv_bfloat16 g_xb[BB * NN * DD];   // visual feats bf16 (raw)
__device__ __nv_bfloat16 g_yb[BB * MM * DD];   // text feats bf16 (raw)
__device__ float g_inv_nx[BB * NN];
__device__ float g_inv_ny[BB * MM];
__device__ float g_K[BB * MM * NN];            // K, then overwritten with P*mask
__device__ float g_u[BB * MM];                 // Sinkhorn u
__device__ float g_v[BB * NN];                 // Sinkhorn v
__device__ float g_vacc[BB * NN];              // Ktu accumulator
__device__ float g_nu[BB * MM];
__device__ float g_partial[BB * MM * 2];

// ---------------- helpers ----------------
__device__ __forceinline__ float warp_sum(float v) {
#pragma unroll
    for (int o = 16; o; o >>= 1) v += __shfl_xor_sync(0xffffffffu, v, o);
    return v;
}

__device__ __forceinline__ float block_sum256(float v, volatile float* red) {
    int tid = threadIdx.x;
    float w = warp_sum(v);
    if ((tid & 31) == 0) red[tid >> 5] = w;
    __syncthreads();
    if (tid < 32) {
        float r = (tid < 8) ? red[tid] : 0.0f;
        r = warp_sum(r);
        if (tid == 0) red[0] = r;
    }
    __syncthreads();
    float out = red[0];
    __syncthreads();
    return out;
}

__device__ __forceinline__ float block_sum288(float v, volatile float* red) {
    int tid = threadIdx.x;
    float w = warp_sum(v);
    if ((tid & 31) == 0) red[tid >> 5] = w;
    __syncthreads();
    if (tid < 32) {
        float r = (tid < 9) ? red[tid] : 0.0f;
        r = warp_sum(r);
        if (tid == 0) red[0] = r;
    }
    __syncthreads();
    return red[0];
}

__device__ __forceinline__ void cluster_sync() {
    asm volatile("barrier.cluster.arrive.aligned;" ::: "memory");
    asm volatile("barrier.cluster.wait.aligned;" ::: "memory");
}

__device__ __forceinline__ void ldsm4(uint32_t* r, uint32_t addr) {
    asm volatile("ldmatrix.sync.aligned.m8n8.x4.shared.b16 {%0,%1,%2,%3}, [%4];"
                 : "=r"(r[0]), "=r"(r[1]), "=r"(r[2]), "=r"(r[3]) : "r"(addr));
}

__device__ __forceinline__ void mma16816(float* c, const uint32_t* a, const uint32_t* b) {
    asm volatile(
        "mma.sync.aligned.m16n8k16.row.col.f32.bf16.bf16.f32 "
        "{%0,%1,%2,%3}, {%4,%5,%6,%7}, {%8,%9}, {%0,%1,%2,%3};"
        : "+f"(c[0]), "+f"(c[1]), "+f"(c[2]), "+f"(c[3])
        : "r"(a[0]), "r"(a[1]), "r"(a[2]), "r"(a[3]), "r"(b[0]), "r"(b[1]));
}

__device__ __forceinline__ void cp16(uint32_t dst, const void* src) {
    asm volatile("cp.async.cg.shared.global [%0], [%1], 16;" :: "r"(dst), "l"(src));
}

// ---------------- kernel 1: norms + bf16 conversion ----------------
__global__ void __launch_bounds__(256) prep_kernel(const float* __restrict__ visual,
                                                   const float* __restrict__ text) {
    int warp = blockIdx.x * 8 + (threadIdx.x >> 5);
    int lane = threadIdx.x & 31;
    const int VROWS = BB * NN;
    const float* src;
    __nv_bfloat16* dst;
    float* invp;
    if (warp < VROWS) {
        src = visual + (size_t)warp * DD;
        dst = g_xb + (size_t)warp * DD;
        invp = g_inv_nx + warp;
    } else {
        int r = warp - VROWS;
        src = text + (size_t)r * DD;
        dst = g_yb + (size_t)r * DD;
        invp = g_inv_ny + r;
    }
    const float4* s4 = (const float4*)src;
    uint2* d2 = (uint2*)dst;
    float ss = 0.0f;
#pragma unroll
    for (int i = 0; i < 8; ++i) {
        float4 v = __ldcs(&s4[lane + 32 * i]);
        ss += v.x * v.x + v.y * v.y + v.z * v.z + v.w * v.w;
        uint32_t lo = (uint32_t)__bfloat16_as_ushort(__float2bfloat16_rn(v.x))
                    | ((uint32_t)__bfloat16_as_ushort(__float2bfloat16_rn(v.y)) << 16);
        uint32_t hi = (uint32_t)__bfloat16_as_ushort(__float2bfloat16_rn(v.z))
                    | ((uint32_t)__bfloat16_as_ushort(__float2bfloat16_rn(v.w)) << 16);
        d2[lane + 32 * i] = make_uint2(lo, hi);
    }
    ss = warp_sum(ss);
    if (lane == 0) *invp = rsqrtf(ss + 1e-12f);
}

// ---------------- kernel 2: HMMA bf16 GEMM, cp.async double-buffered ----------
__global__ void __launch_bounds__(256) gemm_expK_kernel() {
    __shared__ __align__(16) char sa_g[2][128 * 128];
    __shared__ __align__(16) char sb_g[2][64 * 128];
    uint32_t SA = (uint32_t)__cvta_generic_to_shared(&sa_g[0][0]);
    uint32_t SB = (uint32_t)__cvta_generic_to_shared(&sb_g[0][0]);

    int tid = threadIdx.x, wid = tid >> 5, lane = tid & 31;
    int nt = blockIdx.x, mt = blockIdx.y, b = blockIdx.z;
    int wm = wid & 3, wn = wid >> 2;

    const __nv_bfloat16* Abase = g_yb + ((size_t)(b * MM + mt * 128)) * DD;
    const __nv_bfloat16* Bbase = g_xb + ((size_t)(b * NN + nt * 64)) * DD;

    float acc[2][4][4];
#pragma unroll
    for (int i = 0; i < 2; ++i)
#pragma unroll
        for (int j = 0; j < 4; ++j)
#pragma unroll
            for (int k = 0; k < 4; ++k) acc[i][j][k] = 0.0f;

    int a_row0 = wm * 32 + ((lane >> 3) & 1) * 8 + (lane & 7);
    int a_chunk_sel = (lane >> 4);
    int b_row0 = wn * 32 + (lane >> 4) * 8 + (lane & 7);
    int b_chunk_sel = ((lane >> 3) & 1);

    int arow[4], acol[4], brow[2], bcol[2];
    uint32_t adst[4], bdst[2];
#pragma unroll
    for (int q = 0; q < 4; ++q) {
        int c = tid + 256 * q;
        arow[q] = c >> 3; acol[q] = c & 7;
        adst[q] = SA + arow[q] * 128 + ((acol[q] ^ (arow[q] & 7)) * 16);
    }
#pragma unroll
    for (int q = 0; q < 2; ++q) {
        int c = tid + 256 * q;
        brow[q] = c >> 3; bcol[q] = c & 7;
        bdst[q] = SB + brow[q] * 128 + ((bcol[q] ^ (brow[q] & 7)) * 16);
    }

    // issue stage 0
#pragma unroll
    for (int q = 0; q < 4; ++q)
        cp16(adst[q], Abase + (size_t)arow[q] * DD + acol[q] * 8);
#pragma unroll
    for (int q = 0; q < 2; ++q)
        cp16(bdst[q], Bbase + (size_t)brow[q] * DD + bcol[q] * 8);
    asm volatile("cp.async.commit_group;" ::: "memory");

    for (int s = 0; s < 16; ++s) {
        asm volatile("cp.async.wait_group 0;" ::: "memory");
        __syncthreads();
        if (s < 15) {
            int kb = (s + 1) * 64;
            uint32_t boff = ((s + 1) & 1) ? 16384u : 0u;
            uint32_t boffB = ((s + 1) & 1) ? 8192u : 0u;
#pragma unroll
            for (int q = 0; q < 4; ++q)
                cp16(adst[q] + boff, Abase + (size_t)arow[q] * DD + kb + acol[q] * 8);
#pragma unroll
            for (int q = 0; q < 2; ++q)
                cp16(bdst[q] + boffB, Bbase + (size_t)brow[q] * DD + kb + bcol[q] * 8);
            asm volatile("cp.async.commit_group;" ::: "memory");
        }

        uint32_t SAc = SA + ((s & 1) ? 16384u : 0u);
        uint32_t SBc = SB + ((s & 1) ? 8192u : 0u);
#pragma unroll
        for (int kk = 0; kk < 4; ++kk) {
            uint32_t a0[4], a1[4], bA[4], bB[4];
            {
                int row = a_row0;
                int ch = kk * 2 + a_chunk_sel;
                ldsm4(a0, SAc + row * 128 + ((ch ^ (row & 7)) * 16));
                row = a_row0 + 16;
                ldsm4(a1, SAc + row * 128 + ((ch ^ (row & 7)) * 16));
            }
            {
                int row = b_row0;
                int ch = kk * 2 + b_chunk_sel;
                ldsm4(bA, SBc + row * 128 + ((ch ^ (row & 7)) * 16));
                row = b_row0 + 16;
                ldsm4(bB, SBc + row * 128 + ((ch ^ (row & 7)) * 16));
            }
            mma16816(acc[0][0], a0, bA + 0);
            mma16816(acc[0][1], a0, bA + 2);
            mma16816(acc[0][2], a0, bB + 0);
            mma16816(acc[0][3], a0, bB + 2);
            mma16816(acc[1][0], a1, bA + 0);
            mma16816(acc[1][1], a1, bA + 2);
            mma16816(acc[1][2], a1, bB + 0);
            mma16816(acc[1][3], a1, bB + 2);
        }
    }

    // epilogue: scale by inv-norms, exp((cos-1)*10), write g_K
    int mrow_base = mt * 128 + wm * 32 + (lane >> 2);
    int ncol_base = nt * 64 + wn * 32 + (lane & 3) * 2;
    const float* invx = g_inv_nx + b * NN;
    const float* invy = g_inv_ny + b * MM;
#pragma unroll
    for (int mi = 0; mi < 2; ++mi) {
#pragma unroll
        for (int half = 0; half < 2; ++half) {
            int m = mrow_base + mi * 16 + half * 8;
            float invm = invy[m];
            float* out = g_K + ((size_t)(b * MM + m)) * NN;
#pragma unroll
            for (int ni = 0; ni < 4; ++ni) {
                int n = ncol_base + ni * 8;
                float c0 = acc[mi][ni][half * 2 + 0];
                float c1 = acc[mi][ni][half * 2 + 1];
                float s0 = c0 * invm * invx[n];
                float s1 = c1 * invm * invx[n + 1];
                float2 e;
                e.x = __expf((s0 - 1.0f) * 10.0f);
                e.y = __expf((s1 - 1.0f) * 10.0f);
                *(float2*)(out + n) = e;
            }
        }
    }
}

// ---------------- kernel 3: Sinkhorn + teacher finalize (cluster per batch) ----
// grid = 128 CTAs (16 clusters x 8) x 256 threads. CTA owns 32 K-rows (L1-hot).
// Tail overwrites g_K with P_hat * mask (fully normalized teacher row).
__global__ void __cluster_dims__(8, 1, 1) __launch_bounds__(256)
sinkhorn_kernel(const float* __restrict__ mask) {
    __shared__ float vsm[NN];
    __shared__ float usm[32];
    __shared__ float red[8];
    int tid = threadIdx.x;
    int b = blockIdx.x >> 3;
    int rank = blockIdx.x & 7;
    int wid = tid >> 5, lane = tid & 31;

    if (rank == 0) {
        float mv = mask[b * MM + tid];
        float msum = block_sum256(mv, red);
        g_nu[b * MM + tid] = mv / (msum + EPSF);
    }
    if (tid < 72) {
        int col = rank * 72 + tid;
        g_v[b * NN + col] = 1.0f;
        g_vacc[b * NN + col] = 0.0f;
    }
    __threadfence();
    cluster_sync();

    const int row0 = rank * 32;
    float* Kbase = g_K + ((size_t)(b * MM + row0)) * NN;

    for (int it = 0; it < 5; ++it) {
        // ---- phase A: u = (nu / (K v + eps))^fi for our 32 rows ----
        for (int j = tid; j < NN; j += 256) vsm[j] = __ldcg(g_v + b * NN + j);
        __syncthreads();
#pragma unroll
        for (int r = 0; r < 4; ++r) {
            int rl = wid * 4 + r;
            const float* Kr = Kbase + (size_t)rl * NN;
            float acc = 0.0f;
#pragma unroll
            for (int i = 0; i < 18; ++i) {
                int j = lane + 32 * i;
                acc += Kr[j] * vsm[j];
            }
            acc = warp_sum(acc);
            if (lane == 0) {
                int g = b * MM + row0 + rl;
                g_u[g] = __powf(__ldcg(g_nu + g) / (acc + EPSF), FI_C);
            }
        }
        __threadfence();
        cluster_sync();

        // ---- phase B: partial Ktu over our 32 rows ----
        if (tid < 32) usm[tid] = __ldcg(g_u + b * MM + row0 + tid);
        __syncthreads();
        float a0 = 0.0f, a1 = 0.0f, a2 = 0.0f;
#pragma unroll 4
        for (int r = 0; r < 32; ++r) {
            const float* Kr = Kbase + (size_t)r * NN;
            float ur = usm[r];
            a0 += Kr[tid] * ur;
            a1 += Kr[tid + 256] * ur;
            if (tid < 64) a2 += Kr[tid + 512] * ur;
        }
        atomicAdd(g_vacc + b * NN + tid, a0);
        atomicAdd(g_vacc + b * NN + tid + 256, a1);
        if (tid < 64) atomicAdd(g_vacc + b * NN + tid + 512, a2);
        __threadfence();
        cluster_sync();

        if (tid < 72) {
            int col = b * NN + rank * 72 + tid;
            float s = __ldcg(g_vacc + col);
            g_v[col] = __powf(MU_C / (s + EPSF), FI_C);
            g_vacc[col] = 0.0f;
        }
        __threadfence();
        cluster_sync();
    }

    // ---- tail: overwrite K rows with P_hat * mask (teacher finalize) ----
    for (int j = tid; j < NN; j += 256) vsm[j] = __ldcg(g_v + b * NN + j);
    __syncthreads();
#pragma unroll
    for (int r = 0; r < 4; ++r) {
        int rl = wid * 4 + r;
        int g = b * MM + row0 + rl;
        float* Kr = Kbase + (size_t)rl * NN;
        float u = __ldcg(g_u + g);
        float pj[18];
        float rs = 0.0f;
#pragma unroll
        for (int i = 0; i < 18; ++i) {
            int j = lane + 32 * i;
            float p = u * Kr[j] * vsm[j];
            pj[i] = p;
            rs += p;
        }
        rs = warp_sum(rs);
        float scale = mask[g] / (rs + EPSF);
#pragma unroll
        for (int i = 0; i < 18; ++i) {
            int j = lane + 32 * i;
            Kr[j] = pj[i] * scale;
        }
    }
}

// ---------------- loss: pure stream sum P*log(student) ----------------
// grid (4096, 2), block 288 (9 warps = 576/2 float2 lanes, no guards).
__global__ void __launch_bounds__(288) loss_kernel(const float* __restrict__ student) {
    __shared__ float red[9];
    int blk = blockIdx.x, hb = blockIdx.y, tid = threadIdx.x;
    int b = blk >> 8, m = blk & 255;
    const float2* Pr = (const float2*)(g_K + (size_t)blk * NN);
    float2 p = Pr[tid];
    const float* sbase = student + ((size_t)(b * HH + hb * 8) * MM + m) * NN;
    float2 sv[8];
#pragma unroll
    for (int h = 0; h < 8; ++h)
        sv[h] = __ldcs((const float2*)(sbase + (size_t)h * MM * NN) + tid);
    float acc = 0.0f;
#pragma unroll
    for (int h = 0; h < 8; ++h)
        acc += p.x * __logf(sv[h].x + EPSF) + p.y * __logf(sv[h].y + EPSF);
    float tot = block_sum288(acc, red);
    if (tid == 0) g_partial[blk * 2 + hb] = tot;
}

// ---------------- final reduce ----------------
__global__ void __launch_bounds__(256) reduce_kernel(float* __restrict__ out) {
    __shared__ float red[8];
    int tid = threadIdx.x;
    float s = 0.0f;
    for (int i = tid; i < BB * MM * 2; i += 256) s += g_partial[i];
    float t = block_sum256(s, red);
    if (tid == 0) out[0] = -t * (1.0f / (float)(BB * HH * MM));
}

// ---------------- launch ----------------
extern "C" void kernel_launch(void* const* d_in, const int* in_sizes, int n_in,
                              void* d_out, int out_size) {
    const float *student = nullptr, *visual = nullptr, *text = nullptr, *mask = nullptr;
    for (int i = 0; i < n_in; ++i) {
        long sz = in_sizes[i];
        if (sz == (long)BB * HH * MM * NN) student = (const float*)d_in[i];
        else if (sz == (long)BB * NN * DD) visual = (const float*)d_in[i];
        else if (sz == (long)BB * MM * DD) text = (const float*)d_in[i];
        else if (sz == (long)BB * MM) mask = (const float*)d_in[i];
    }
    float* out = (float*)d_out;

    prep_kernel<<<(BB * NN + BB * MM) / 8, 256>>>(visual, text);
    gemm_expK_kernel<<<dim3(NN / 64, MM / 128, BB), 256>>>();
    sinkhorn_kernel<<<128, 256>>>(mask);
    loss_kernel<<<dim3(BB * MM, 2), 288>>>(student);
    reduce_kernel<<<1, 256>>>(out);
}

// round 7
// speedup vs baseline: 1.8892x; 1.1193x over previous
#include <cuda_runtime.h>
#include <cuda_bf16.h>
#include <cstdint>

// Problem constants: B=16, H=16, M=256, N=576, D=1024
#define BB 16
#define HH 16
#define MM 256
#define NN 576
#define DD 1024

#define EPSF 1e-8f
#define MU_C (1.0f / 576.0f)
#define FI_C (1.0f / 1.1f)

// ---------------- device scratch ----------------
__device__ __nv_bfloat16 g_xb[BB * NN * DD];   // visual feats bf16 (raw)
__device__ __nv_bfloat16 g_yb[BB * MM * DD];   // text feats bf16 (raw)
__device__ float g_inv_nx[BB * NN];
__device__ float g_inv_ny[BB * MM];
__device__ float g_K[BB * MM * NN];            // K, then overwritten with P*mask
__device__ float g_vpart[2][8][BB * NN];       // per-rank partial Ktu (parity buffered)
__device__ float g_partial[BB * MM * 2];
__device__ unsigned g_done;

// ---------------- helpers ----------------
__device__ __forceinline__ float warp_sum(float v) {
#pragma unroll
    for (int o = 16; o; o >>= 1) v += __shfl_xor_sync(0xffffffffu, v, o);
    return v;
}

__device__ __forceinline__ float block_sum256(float v, volatile float* red) {
    int tid = threadIdx.x;
    float w = warp_sum(v);
    if ((tid & 31) == 0) red[tid >> 5] = w;
    __syncthreads();
    if (tid < 32) {
        float r = (tid < 8) ? red[tid] : 0.0f;
        r = warp_sum(r);
        if (tid == 0) red[0] = r;
    }
    __syncthreads();
    float out = red[0];
    __syncthreads();
    return out;
}

__device__ __forceinline__ float block_sum288(float v, volatile float* red) {
    int tid = threadIdx.x;
    float w = warp_sum(v);
    if ((tid & 31) == 0) red[tid >> 5] = w;
    __syncthreads();
    if (tid < 32) {
        float r = (tid < 9) ? red[tid] : 0.0f;
        r = warp_sum(r);
        if (tid == 0) red[0] = r;
    }
    __syncthreads();
    return red[0];
}

__device__ __forceinline__ void cluster_sync() {
    asm volatile("barrier.cluster.arrive.aligned;" ::: "memory");
    asm volatile("barrier.cluster.wait.aligned;" ::: "memory");
}

__device__ __forceinline__ void ldsm4(uint32_t* r, uint32_t addr) {
    asm volatile("ldmatrix.sync.aligned.m8n8.x4.shared.b16 {%0,%1,%2,%3}, [%4];"
                 : "=r"(r[0]), "=r"(r[1]), "=r"(r[2]), "=r"(r[3]) : "r"(addr));
}

__device__ __forceinline__ void mma16816(float* c, const uint32_t* a, const uint32_t* b) {
    asm volatile(
        "mma.sync.aligned.m16n8k16.row.col.f32.bf16.bf16.f32 "
        "{%0,%1,%2,%3}, {%4,%5,%6,%7}, {%8,%9}, {%0,%1,%2,%3};"
        : "+f"(c[0]), "+f"(c[1]), "+f"(c[2]), "+f"(c[3])
        : "r"(a[0]), "r"(a[1]), "r"(a[2]), "r"(a[3]), "r"(b[0]), "r"(b[1]));
}

__device__ __forceinline__ void cp16(uint32_t dst, const void* src) {
    asm volatile("cp.async.cg.shared.global [%0], [%1], 16;" :: "r"(dst), "l"(src));
}

// ---------------- kernel 1: norms + bf16 conversion ----------------
__global__ void __launch_bounds__(256) prep_kernel(const float* __restrict__ visual,
                                                   const float* __restrict__ text) {
    int warp = blockIdx.x * 8 + (threadIdx.x >> 5);
    int lane = threadIdx.x & 31;
    const int VROWS = BB * NN;
    const float* src;
    __nv_bfloat16* dst;
    float* invp;
    if (warp < VROWS) {
        src = visual + (size_t)warp * DD;
        dst = g_xb + (size_t)warp * DD;
        invp = g_inv_nx + warp;
    } else {
        int r = warp - VROWS;
        src = text + (size_t)r * DD;
        dst = g_yb + (size_t)r * DD;
        invp = g_inv_ny + r;
    }
    const float4* s4 = (const float4*)src;
    uint2* d2 = (uint2*)dst;
    float ss = 0.0f;
#pragma unroll
    for (int i = 0; i < 8; ++i) {
        float4 v = __ldcs(&s4[lane + 32 * i]);
        ss += v.x * v.x + v.y * v.y + v.z * v.z + v.w * v.w;
        uint32_t lo = (uint32_t)__bfloat16_as_ushort(__float2bfloat16_rn(v.x))
                    | ((uint32_t)__bfloat16_as_ushort(__float2bfloat16_rn(v.y)) << 16);
        uint32_t hi = (uint32_t)__bfloat16_as_ushort(__float2bfloat16_rn(v.z))
                    | ((uint32_t)__bfloat16_as_ushort(__float2bfloat16_rn(v.w)) << 16);
        d2[lane + 32 * i] = make_uint2(lo, hi);
    }
    ss = warp_sum(ss);
    if (lane == 0) *invp = rsqrtf(ss + 1e-12f);
}

// ---------------- kernel 2: HMMA bf16 GEMM, 3-stage cp.async pipeline --------
// grid: (nt=9, mt=2, b=16); block 256 = 8 warps (4 x 2). Dynamic smem 72 KB.
#define ASTG 16384
#define BSTG 8192
__global__ void __launch_bounds__(256) gemm_expK_kernel() {
    extern __shared__ __align__(16) char dsm[];
    uint32_t SBASE = (uint32_t)__cvta_generic_to_shared(dsm);
    uint32_t SA = SBASE;                 // 3 x 16384
    uint32_t SB = SBASE + 3 * ASTG;      // 3 x 8192

    int tid = threadIdx.x, wid = tid >> 5, lane = tid & 31;
    int nt = blockIdx.x, mt = blockIdx.y, b = blockIdx.z;
    int wm = wid & 3, wn = wid >> 2;

    const __nv_bfloat16* Abase = g_yb + ((size_t)(b * MM + mt * 128)) * DD;
    const __nv_bfloat16* Bbase = g_xb + ((size_t)(b * NN + nt * 64)) * DD;

    float acc[2][4][4];
#pragma unroll
    for (int i = 0; i < 2; ++i)
#pragma unroll
        for (int j = 0; j < 4; ++j)
#pragma unroll
            for (int k = 0; k < 4; ++k) acc[i][j][k] = 0.0f;

    int a_row0 = wm * 32 + ((lane >> 3) & 1) * 8 + (lane & 7);
    int a_chunk_sel = (lane >> 4);
    int b_row0 = wn * 32 + (lane >> 4) * 8 + (lane & 7);
    int b_chunk_sel = ((lane >> 3) & 1);

    int arow[4], acol[4], brow[2], bcol[2];
    uint32_t aoff[4], boff[2];
#pragma unroll
    for (int q = 0; q < 4; ++q) {
        int c = tid + 256 * q;
        arow[q] = c >> 3; acol[q] = c & 7;
        aoff[q] = arow[q] * 128 + ((acol[q] ^ (arow[q] & 7)) * 16);
    }
#pragma unroll
    for (int q = 0; q < 2; ++q) {
        int c = tid + 256 * q;
        brow[q] = c >> 3; bcol[q] = c & 7;
        boff[q] = brow[q] * 128 + ((bcol[q] ^ (brow[q] & 7)) * 16);
    }

#define ISSUE(s)                                                               \
    do {                                                                       \
        int st_ = (s) % 3;                                                     \
        int kb_ = (s) * 64;                                                    \
        uint32_t ab_ = SA + st_ * ASTG, bb_ = SB + st_ * BSTG;                 \
        _Pragma("unroll")                                                      \
        for (int q = 0; q < 4; ++q)                                            \
            cp16(ab_ + aoff[q], Abase + (size_t)arow[q] * DD + kb_ + acol[q] * 8); \
        _Pragma("unroll")                                                      \
        for (int q = 0; q < 2; ++q)                                            \
            cp16(bb_ + boff[q], Bbase + (size_t)brow[q] * DD + kb_ + bcol[q] * 8); \
        asm volatile("cp.async.commit_group;" ::: "memory");                   \
    } while (0)

    ISSUE(0);
    ISSUE(1);

    for (int s = 0; s < 16; ++s) {
        if (s == 15)
            asm volatile("cp.async.wait_group 0;" ::: "memory");
        else
            asm volatile("cp.async.wait_group 1;" ::: "memory");
        __syncthreads();
        if (s + 2 < 16) ISSUE(s + 2);

        uint32_t SAc = SA + (s % 3) * ASTG;
        uint32_t SBc = SB + (s % 3) * BSTG;
#pragma unroll
        for (int kk = 0; kk < 4; ++kk) {
            uint32_t a0[4], a1[4], bA[4], bB[4];
            {
                int row = a_row0;
                int ch = kk * 2 + a_chunk_sel;
                ldsm4(a0, SAc + row * 128 + ((ch ^ (row & 7)) * 16));
                row = a_row0 + 16;
                ldsm4(a1, SAc + row * 128 + ((ch ^ (row & 7)) * 16));
            }
            {
                int row = b_row0;
                int ch = kk * 2 + b_chunk_sel;
                ldsm4(bA, SBc + row * 128 + ((ch ^ (row & 7)) * 16));
                row = b_row0 + 16;
                ldsm4(bB, SBc + row * 128 + ((ch ^ (row & 7)) * 16));
            }
            mma16816(acc[0][0], a0, bA + 0);
            mma16816(acc[0][1], a0, bA + 2);
            mma16816(acc[0][2], a0, bB + 0);
            mma16816(acc[0][3], a0, bB + 2);
            mma16816(acc[1][0], a1, bA + 0);
            mma16816(acc[1][1], a1, bA + 2);
            mma16816(acc[1][2], a1, bB + 0);
            mma16816(acc[1][3], a1, bB + 2);
        }
    }

    // epilogue: scale by inv-norms, exp((cos-1)*10), write g_K
    int mrow_base = mt * 128 + wm * 32 + (lane >> 2);
    int ncol_base = nt * 64 + wn * 32 + (lane & 3) * 2;
    const float* invx = g_inv_nx + b * NN;
    const float* invy = g_inv_ny + b * MM;
#pragma unroll
    for (int mi = 0; mi < 2; ++mi) {
#pragma unroll
        for (int half = 0; half < 2; ++half) {
            int m = mrow_base + mi * 16 + half * 8;
            float invm = invy[m];
            float* out = g_K + ((size_t)(b * MM + m)) * NN;
#pragma unroll
            for (int ni = 0; ni < 4; ++ni) {
                int n = ncol_base + ni * 8;
                float c0 = acc[mi][ni][half * 2 + 0];
                float c1 = acc[mi][ni][half * 2 + 1];
                float s0 = c0 * invm * invx[n];
                float s1 = c1 * invm * invx[n + 1];
                float2 e;
                e.x = __expf((s0 - 1.0f) * 10.0f);
                e.y = __expf((s1 - 1.0f) * 10.0f);
                *(float2*)(out + n) = e;
            }
        }
    }
}

// ---------------- kernel 3: Sinkhorn + teacher finalize (cluster per batch) ----
// grid = 128 CTAs (16 clusters x 8) x 256 threads. CTA owns 32 K-rows (L1-hot).
// u is CTA-local (smem only). Phase B writes per-rank column partials into a
// parity double buffer -> exactly ONE cluster sync per iteration, no atomics.
__global__ void __cluster_dims__(8, 1, 1) __launch_bounds__(256)
sinkhorn_kernel(const float* __restrict__ mask) {
    __shared__ float vsm[NN];
    __shared__ float usm[32];
    __shared__ float masksm[32];
    __shared__ float nusm[32];
    __shared__ float red[8];
    int tid = threadIdx.x;
    int b = blockIdx.x >> 3;
    int rank = blockIdx.x & 7;
    int wid = tid >> 5, lane = tid & 31;
    const int row0 = rank * 32;

    // local nu = mask/msum for own 32 rows (every CTA computes its own msum)
    float mv = mask[b * MM + tid];
    float msum = block_sum256(mv, red);
    if (tid < 32) {
        float mk = mask[b * MM + row0 + tid];
        masksm[tid] = mk;
        nusm[tid] = mk / (msum + EPSF);
    }
    __syncthreads();

    float* Kbase = g_K + ((size_t)(b * MM + row0)) * NN;

    for (int it = 0; it < 5; ++it) {
        // ---- build v in smem from previous iteration's partials ----
        if (it == 0) {
            for (int j = tid; j < NN; j += 256) vsm[j] = 1.0f;
        } else {
            const float (*vp)[BB * NN] = g_vpart[(it - 1) & 1];
            for (int j = tid; j < NN; j += 256) {
                float s = 0.0f;
#pragma unroll
                for (int r = 0; r < 8; ++r) s += __ldcg(&vp[r][b * NN + j]);
                vsm[j] = __powf(MU_C / (s + EPSF), FI_C);
            }
        }
        __syncthreads();

        // ---- phase A: u for own 32 rows (CTA-local) ----
#pragma unroll
        for (int r = 0; r < 4; ++r) {
            int rl = wid * 4 + r;
            const float* Kr = Kbase + (size_t)rl * NN;
            float acc = 0.0f;
#pragma unroll
            for (int i = 0; i < 18; ++i) {
                int j = lane + 32 * i;
                acc += Kr[j] * vsm[j];
            }
            acc = warp_sum(acc);
            if (lane == 0) usm[rl] = __powf(nusm[rl] / (acc + EPSF), FI_C);
        }
        __syncthreads();

        // ---- phase B: partial Ktu over own rows -> own vpart slice ----
        float a0 = 0.0f, a1 = 0.0f, a2 = 0.0f;
#pragma unroll 4
        for (int r = 0; r < 32; ++r) {
            const float* Kr = Kbase + (size_t)r * NN;
            float ur = usm[r];
            a0 += Kr[tid] * ur;
            a1 += Kr[tid + 256] * ur;
            if (tid < 64) a2 += Kr[tid + 512] * ur;
        }
        float* vp = g_vpart[it & 1][rank] + b * NN;
        vp[tid] = a0;
        vp[tid + 256] = a1;
        if (tid < 64) vp[tid + 512] = a2;
        __threadfence();
        cluster_sync();
    }

    // ---- tail: final v (phase B of it=4 wrote buffer 0), then P finalize ----
    {
        const float (*vp)[BB * NN] = g_vpart[0];
        for (int j = tid; j < NN; j += 256) {
            float s = 0.0f;
#pragma unroll
            for (int r = 0; r < 8; ++r) s += __ldcg(&vp[r][b * NN + j]);
            vsm[j] = __powf(MU_C / (s + EPSF), FI_C);
        }
    }
    __syncthreads();
#pragma unroll
    for (int r = 0; r < 4; ++r) {
        int rl = wid * 4 + r;
        float* Kr = Kbase + (size_t)rl * NN;
        float u = usm[rl];
        float pj[18];
        float rs = 0.0f;
#pragma unroll
        for (int i = 0; i < 18; ++i) {
            int j = lane + 32 * i;
            float p = u * Kr[j] * vsm[j];
            pj[i] = p;
            rs += p;
        }
        rs = warp_sum(rs);
        float scale = masksm[rl] / (rs + EPSF);
#pragma unroll
        for (int i = 0; i < 18; ++i) {
            int j = lane + 32 * i;
            Kr[j] = pj[i] * scale;
        }
    }
}

// ---------------- loss + fused final reduce ----------------
// grid (4096, 2), block 288 (9 warps = 576/2 float2 lanes, no guards).
// Last block (deterministic counter) does the final fixed-order reduction.
__global__ void __launch_bounds__(288) loss_kernel(const float* __restrict__ student,
                                                   float* __restrict__ out) {
    __shared__ float red[9];
    __shared__ bool last;
    int blk = blockIdx.x, hb = blockIdx.y, tid = threadIdx.x;
    int b = blk >> 8, m = blk & 255;
    const float2* Pr = (const float2*)(g_K + (size_t)blk * NN);
    float2 p = Pr[tid];
    const float* sbase = student + ((size_t)(b * HH + hb * 8) * MM + m) * NN;
    float2 sv[8];
#pragma unroll
    for (int h = 0; h < 8; ++h)
        sv[h] = __ldcs((const float2*)(sbase + (size_t)h * MM * NN) + tid);
    float acc = 0.0f;
#pragma unroll
    for (int h = 0; h < 8; ++h)
        acc += p.x * __logf(sv[h].x + EPSF) + p.y * __logf(sv[h].y + EPSF);
    float tot = block_sum288(acc, red);
    if (tid == 0) g_partial[blk * 2 + hb] = tot;
    __threadfence();
    if (tid == 0) {
        unsigned t = atomicAdd(&g_done, 1u);
        last = (t == (unsigned)(BB * MM * 2 - 1));
    }
    __syncthreads();
    if (last) {
        if (tid == 0) g_done = 0;  // reset for next graph replay
        float s = 0.0f;
        for (int i = tid; i < BB * MM * 2; i += 288) s += g_partial[i];
        float t2 = block_sum288(s, red);
        if (tid == 0) out[0] = -t2 * (1.0f / (float)(BB * HH * MM));
    }
}

// ---------------- launch ----------------
extern "C" void kernel_launch(void* const* d_in, const int* in_sizes, int n_in,
                              void* d_out, int out_size) {
    const float *student = nullptr, *visual = nullptr, *text = nullptr, *mask = nullptr;
    for (int i = 0; i < n_in; ++i) {
        long sz = in_sizes[i];
        if (sz == (long)BB * HH * MM * NN) student = (const float*)d_in[i];
        else if (sz == (long)BB * NN * DD) visual = (const float*)d_in[i];
        else if (sz == (long)BB * MM * DD) text = (const float*)d_in[i];
        else if (sz == (long)BB * MM) mask = (const float*)d_in[i];
    }
    float* out = (float*)d_out;

    static bool attr_done = false;
    if (!attr_done) {
        cudaFuncSetAttribute(gemm_expK_kernel,
                             cudaFuncAttributeMaxDynamicSharedMemorySize,
                             3 * (ASTG + BSTG));
        attr_done = true;
    }

    prep_kernel<<<(BB * NN + BB * MM) / 8, 256>>>(visual, text);
    gemm_expK_kernel<<<dim3(NN / 64, MM / 128, BB), 256, 3 * (ASTG + BSTG)>>>();
    sinkhorn_kernel<<<128, 256>>>(mask);
    loss_kernel<<<dim3(BB * MM, 2), 288>>>(student, out);
}